// round 2
// baseline (speedup 1.0000x reference)
#include <cuda_runtime.h>
#include <math.h>

// Problem constants
#define SS 1024
#define BB 16
#define DD 512
#define HH 8
#define KK 64

// Scratch: [B,H,S,K] fp32 each = 32 MB; 4 arrays = 128 MB static device mem.
__device__ float g_wq[BB * HH * SS * KK];
__device__ float g_wk[BB * HH * SS * KK];
__device__ float g_wv[BB * HH * SS * KK];
__device__ float g_att[BB * HH * SS * KK];

// ---------------------------------------------------------------------------
// Kernel 1: per-head projection + L2 normalize.
//   dst[b,h,s,k] = normalize_k( sum_d in[s,b,d] * W[h,k,d] )
// grid = (S/64, B*H, 3), block = (16,16). Output tile = 64 (s) x 64 (k = full K).
// ---------------------------------------------------------------------------
__global__ __launch_bounds__(256) void proj_norm_kernel(
    const float* __restrict__ q, const float* __restrict__ k,
    const float* __restrict__ v, const float* __restrict__ WQ,
    const float* __restrict__ WK, const float* __restrict__ WV)
{
    const float* in; const float* W; float* dst;
    if (blockIdx.z == 0)      { in = q; W = WQ; dst = g_wq; }
    else if (blockIdx.z == 1) { in = k; W = WK; dst = g_wk; }
    else                      { in = v; W = WV; dst = g_wv; }

    const int s0 = blockIdx.x * 64;
    const int bh = blockIdx.y;          // b*H + h
    const int b  = bh / HH;
    const int h  = bh % HH;

    __shared__ float As[64][33];        // input rows  (s, d-chunk)
    __shared__ float Bs[64][33];        // weight rows (k, d-chunk)
    __shared__ float Ts[64][65];        // output tile for normalization
    __shared__ float inv_nrm[64];

    const int tx  = threadIdx.x;
    const int ty  = threadIdx.y;
    const int tid = ty * 16 + tx;

    const float* inb = in + (size_t)b * DD;          // row stride B*D
    const float* Wh  = W + (size_t)h * KK * DD;

    float acc[4][4] = {};

    for (int d0 = 0; d0 < DD; d0 += 32) {
        #pragma unroll
        for (int l = tid; l < 64 * 32; l += 256) {
            int r = l >> 5, c = l & 31;
            As[r][c] = inb[(size_t)(s0 + r) * (BB * DD) + d0 + c];
            Bs[r][c] = Wh[(size_t)r * DD + d0 + c];
        }
        __syncthreads();
        #pragma unroll
        for (int d = 0; d < 32; d++) {
            float a[4], w[4];
            #pragma unroll
            for (int i = 0; i < 4; i++) a[i] = As[ty + 16 * i][d];
            #pragma unroll
            for (int j = 0; j < 4; j++) w[j] = Bs[tx + 16 * j][d];
            #pragma unroll
            for (int i = 0; i < 4; i++)
                #pragma unroll
                for (int j = 0; j < 4; j++)
                    acc[i][j] = fmaf(a[i], w[j], acc[i][j]);
        }
        __syncthreads();
    }

    // Stage to shared for row-wise L2 norm
    #pragma unroll
    for (int i = 0; i < 4; i++)
        #pragma unroll
        for (int j = 0; j < 4; j++)
            Ts[ty + 16 * i][tx + 16 * j] = acc[i][j];
    __syncthreads();

    if (tid < 64) {
        float s = 0.f;
        #pragma unroll
        for (int c = 0; c < 64; c++) {
            float x = Ts[tid][c];
            s = fmaf(x, x, s);
        }
        inv_nrm[tid] = 1.0f / fmaxf(sqrtf(s), 1e-12f);
    }
    __syncthreads();

    float* dstp = dst + ((size_t)bh * SS + s0) * KK;
    #pragma unroll
    for (int i = 0; i < 4; i++) {
        int r = ty + 16 * i;
        float inv = inv_nrm[r];
        #pragma unroll
        for (int j = 0; j < 4; j++) {
            int c = tx + 16 * j;
            dstp[(size_t)r * KK + c] = Ts[r][c] * inv;
        }
    }
}

// ---------------------------------------------------------------------------
// Kernel 2: streaming attention, no-max softmax (scores bounded in [-1/8,1/8]).
//   g_att[b,h,s,:] = softmax(wq wk^T / 8) wv
// grid = (S/64, B*H), block = (16,16). 64x64 q-tile, k-tiles of 64.
// Dynamic smem: Qs,Ks,Vs,Ps each [64][65] = 66560 B.
// ---------------------------------------------------------------------------
__global__ __launch_bounds__(256) void attn_kernel()
{
    extern __shared__ float smem[];
    float* Qs = smem;                 // [64][65]
    float* Ks = Qs + 64 * 65;
    float* Vs = Ks + 64 * 65;
    float* Ps = Vs + 64 * 65;
    __shared__ float lrow[64];

    const int s0 = blockIdx.x * 64;
    const int bh = blockIdx.y;

    const float* Qp = g_wq + (size_t)bh * SS * KK;
    const float* Kp = g_wk + (size_t)bh * SS * KK;
    const float* Vp = g_wv + (size_t)bh * SS * KK;

    const int tx  = threadIdx.x;
    const int ty  = threadIdx.y;
    const int tid = ty * 16 + tx;

    // Load Q tile once (visible after first sync inside the loop)
    #pragma unroll
    for (int l = tid; l < 64 * 64; l += 256) {
        int r = l >> 6, c = l & 63;
        Qs[r * 65 + c] = Qp[(size_t)(s0 + r) * KK + c];
    }

    float o[4][4] = {};
    float lacc = 0.f;                 // row-sum of exp, valid for tid<64

    for (int t0 = 0; t0 < SS; t0 += 64) {
        #pragma unroll
        for (int l = tid; l < 64 * 64; l += 256) {
            int r = l >> 6, c = l & 63;
            Ks[r * 65 + c] = Kp[(size_t)(t0 + r) * KK + c];
            Vs[r * 65 + c] = Vp[(size_t)(t0 + r) * KK + c];
        }
        __syncthreads();

        // scores: 4x4 fragment per thread over (q = ty+16i, t = tx+16j)
        float sc[4][4] = {};
        #pragma unroll
        for (int d = 0; d < 64; d++) {
            float a[4], kb[4];
            #pragma unroll
            for (int i = 0; i < 4; i++) a[i] = Qs[(ty + 16 * i) * 65 + d];
            #pragma unroll
            for (int j = 0; j < 4; j++) kb[j] = Ks[(tx + 16 * j) * 65 + d];
            #pragma unroll
            for (int i = 0; i < 4; i++)
                #pragma unroll
                for (int j = 0; j < 4; j++)
                    sc[i][j] = fmaf(a[i], kb[j], sc[i][j]);
        }
        // exp (no max needed: |score/8| <= 1/8)
        #pragma unroll
        for (int i = 0; i < 4; i++)
            #pragma unroll
            for (int j = 0; j < 4; j++)
                Ps[(ty + 16 * i) * 65 + (tx + 16 * j)] = __expf(sc[i][j] * 0.125f);
        __syncthreads();

        if (tid < 64) {
            float s = 0.f;
            #pragma unroll
            for (int t = 0; t < 64; t++) s += Ps[tid * 65 + t];
            lacc += s;
        }

        // O += P @ V : fragment over (q = ty+16i, kd = tx+16j)
        #pragma unroll
        for (int t = 0; t < 64; t++) {
            float p[4], vv[4];
            #pragma unroll
            for (int i = 0; i < 4; i++) p[i] = Ps[(ty + 16 * i) * 65 + t];
            #pragma unroll
            for (int j = 0; j < 4; j++) vv[j] = Vs[t * 65 + (tx + 16 * j)];
            #pragma unroll
            for (int i = 0; i < 4; i++)
                #pragma unroll
                for (int j = 0; j < 4; j++)
                    o[i][j] = fmaf(p[i], vv[j], o[i][j]);
        }
        __syncthreads();
    }

    if (tid < 64) lrow[tid] = lacc;
    __syncthreads();

    float* outp = g_att + ((size_t)bh * SS + s0) * KK;
    #pragma unroll
    for (int i = 0; i < 4; i++) {
        int r = ty + 16 * i;
        float inv = 1.0f / lrow[r];
        #pragma unroll
        for (int j = 0; j < 4; j++) {
            int c = tx + 16 * j;
            outp[(size_t)r * KK + c] = o[i][j] * inv;
        }
    }
}

// ---------------------------------------------------------------------------
// Kernel 3: output projection.
//   out[s,b,d] = sum_{h,k} g_att[b,h,s,k] * Wout[d, h*K+k]
// GEMM: M = S*B = 16384 (m = s*B+b), N = D = 512, inner = H*K = 512.
// grid = (D/64, M/64), block = (16,16).
// ---------------------------------------------------------------------------
__global__ __launch_bounds__(256) void outproj_kernel(
    const float* __restrict__ Wout, float* __restrict__ out)
{
    const int d0 = blockIdx.x * 64;
    const int m0 = blockIdx.y * 64;

    __shared__ float As[64][33];      // concat rows (m, j-chunk)
    __shared__ float Bs[64][33];      // Wout rows   (d, j-chunk)

    const int tx  = threadIdx.x;
    const int ty  = threadIdx.y;
    const int tid = ty * 16 + tx;

    float acc[4][4] = {};

    for (int j0 = 0; j0 < HH * KK; j0 += 32) {
        #pragma unroll
        for (int l = tid; l < 64 * 32; l += 256) {
            int r = l >> 5, c = l & 31;
            int m = m0 + r;
            int b = m & (BB - 1);
            int s = m >> 4;
            int jc = j0 + c;
            int h  = jc >> 6;        // j0 is multiple of 32 -> h fixed per chunk row
            int kk = jc & 63;
            As[r][c] = g_att[(((size_t)(b * HH + h)) * SS + s) * KK + kk];
            Bs[r][c] = Wout[(size_t)(d0 + r) * (HH * KK) + jc];
        }
        __syncthreads();
        #pragma unroll
        for (int d = 0; d < 32; d++) {
            float a[4], w[4];
            #pragma unroll
            for (int i = 0; i < 4; i++) a[i] = As[ty + 16 * i][d];
            #pragma unroll
            for (int j = 0; j < 4; j++) w[j] = Bs[tx + 16 * j][d];
            #pragma unroll
            for (int i = 0; i < 4; i++)
                #pragma unroll
                for (int j = 0; j < 4; j++)
                    acc[i][j] = fmaf(a[i], w[j], acc[i][j]);
        }
        __syncthreads();
    }

    #pragma unroll
    for (int i = 0; i < 4; i++) {
        int m = m0 + ty + 16 * i;
        #pragma unroll
        for (int j = 0; j < 4; j++) {
            int d = d0 + tx + 16 * j;
            out[(size_t)m * DD + d] = acc[i][j];
        }
    }
}

// ---------------------------------------------------------------------------
extern "C" void kernel_launch(void* const* d_in, const int* in_sizes, int n_in,
                              void* d_out, int out_size)
{
    const float* q    = (const float*)d_in[0];
    const float* k    = (const float*)d_in[1];
    const float* v    = (const float*)d_in[2];
    const float* WQ   = (const float*)d_in[3];
    const float* WK   = (const float*)d_in[4];
    const float* WV   = (const float*)d_in[5];
    const float* Wout = (const float*)d_in[6];
    float* out = (float*)d_out;

    const int attn_smem = 4 * 64 * 65 * (int)sizeof(float);  // 66560 B
    cudaFuncSetAttribute(attn_kernel,
                         cudaFuncAttributeMaxDynamicSharedMemorySize, attn_smem);

    dim3 blk(16, 16);
    proj_norm_kernel<<<dim3(SS / 64, BB * HH, 3), blk>>>(q, k, v, WQ, WK, WV);
    attn_kernel<<<dim3(SS / 64, BB * HH), blk, attn_smem>>>();
    outproj_kernel<<<dim3(DD / 64, (SS * BB) / 64), blk>>>(Wout, out);
}

// round 4
// speedup vs baseline: 1.8109x; 1.8109x over previous
#include <cuda_runtime.h>
#include <math.h>

#define SS 1024
#define BB 16
#define DD 512
#define HH 8
#define KK 64

using ull = unsigned long long;

__device__ float g_wq[BB * HH * SS * KK];
__device__ float g_wk[BB * HH * SS * KK];
__device__ float g_wv[BB * HH * SS * KK];
__device__ float g_att[BB * HH * SS * KK];

// ---- f32x2 packed-FMA helpers (Blackwell FFMA2 path, PTX-only) -------------
__device__ __forceinline__ ull pk2(float x, float y) {
    ull r; asm("mov.b64 %0, {%1, %2};" : "=l"(r) : "f"(x), "f"(y)); return r;
}
__device__ __forceinline__ void fma2(ull& d, ull a, ull b) {
    asm("fma.rn.f32x2 %0, %1, %2, %0;" : "+l"(d) : "l"(a), "l"(b));
}
__device__ __forceinline__ float2 upk(ull a) {
    float2 f; asm("mov.b64 {%0, %1}, %2;" : "=f"(f.x), "=f"(f.y) : "l"(a)); return f;
}

// ---------------------------------------------------------------------------
// Kernel 1: fused projection + L2 norm as ONE GEMM.
//   C[m][n] = sum_d In_t[m][d] * W_t[n'][d],  m = s*16+b in [0,16384),
//   n in [0,1536): t = n>>9 selects (q,WQ,g_wq)/(k,WK,g_wk)/(v,WV,g_wv),
//   n' = n & 511, h = n' >> 6.  Block tile 128(M) x 64(N), kc=16, 256 thr,
//   8x4 per-thread fragment via f32x2. Each 64-wide n-block == one head, so
//   the row L2-norm is block-local (shfl over 16 lanes).
// ---------------------------------------------------------------------------
__global__ __launch_bounds__(256) void proj_norm_kernel(
    const float* __restrict__ q, const float* __restrict__ kin,
    const float* __restrict__ v, const float* __restrict__ WQ,
    const float* __restrict__ WK, const float* __restrict__ WV)
{
    const int n0 = blockIdx.x * 64;        // 0..1472
    const int m0 = blockIdx.y * 128;
    const int t  = n0 >> 9;
    const int nr = n0 & 511;
    const int h  = nr >> 6;

    const float* In = (t == 0) ? q : (t == 1) ? kin : v;            // [16384][512]
    const float* W  = ((t == 0) ? WQ : (t == 1) ? WK : WV) + (size_t)nr * DD;
    float* dst      = (t == 0) ? g_wq : (t == 1) ? g_wk : g_wv;

    __shared__ __align__(16) float As[2][16][132];   // [k][m], padded
    __shared__ __align__(16) float Bs[2][16][68];    // [k][n], padded

    const int tid  = threadIdx.x;
    const int tx   = tid & 15, ty = tid >> 4;
    const int msub = ty * 8, nsub = tx * 4;

    // loader coords
    const int rA = tid >> 2;               // 0..63
    const int cA = (tid & 3) * 4;          // 0,4,8,12

    ull acc[8][2] = {};

    // preload tile 0
    {
        float4 a0 = *(const float4*)&In[(size_t)(m0 + rA) * DD + cA];
        float4 a1 = *(const float4*)&In[(size_t)(m0 + rA + 64) * DD + cA];
        float4 b0 = *(const float4*)&W[(size_t)rA * DD + cA];
        As[0][cA + 0][rA] = a0.x; As[0][cA + 1][rA] = a0.y;
        As[0][cA + 2][rA] = a0.z; As[0][cA + 3][rA] = a0.w;
        As[0][cA + 0][rA + 64] = a1.x; As[0][cA + 1][rA + 64] = a1.y;
        As[0][cA + 2][rA + 64] = a1.z; As[0][cA + 3][rA + 64] = a1.w;
        Bs[0][cA + 0][rA] = b0.x; Bs[0][cA + 1][rA] = b0.y;
        Bs[0][cA + 2][rA] = b0.z; Bs[0][cA + 3][rA] = b0.w;
    }
    __syncthreads();

    int buf = 0;
    for (int d0 = 0; d0 < DD; d0 += 16) {
        const bool has_next = (d0 + 16) < DD;
        float4 pa0, pa1, pb;
        if (has_next) {
            pa0 = *(const float4*)&In[(size_t)(m0 + rA) * DD + d0 + 16 + cA];
            pa1 = *(const float4*)&In[(size_t)(m0 + rA + 64) * DD + d0 + 16 + cA];
            pb  = *(const float4*)&W[(size_t)rA * DD + d0 + 16 + cA];
        }
        #pragma unroll
        for (int k = 0; k < 16; k++) {
            float4 A0 = *(const float4*)&As[buf][k][msub];
            float4 A1 = *(const float4*)&As[buf][k][msub + 4];
            ulonglong2 Wv = *(const ulonglong2*)&Bs[buf][k][nsub];
            float av[8] = {A0.x, A0.y, A0.z, A0.w, A1.x, A1.y, A1.z, A1.w};
            #pragma unroll
            for (int i = 0; i < 8; i++) {
                ull d = pk2(av[i], av[i]);
                fma2(acc[i][0], d, Wv.x);
                fma2(acc[i][1], d, Wv.y);
            }
        }
        if (has_next) {
            int nb = buf ^ 1;
            As[nb][cA + 0][rA] = pa0.x; As[nb][cA + 1][rA] = pa0.y;
            As[nb][cA + 2][rA] = pa0.z; As[nb][cA + 3][rA] = pa0.w;
            As[nb][cA + 0][rA + 64] = pa1.x; As[nb][cA + 1][rA + 64] = pa1.y;
            As[nb][cA + 2][rA + 64] = pa1.z; As[nb][cA + 3][rA + 64] = pa1.w;
            Bs[nb][cA + 0][rA] = pb.x; Bs[nb][cA + 1][rA] = pb.y;
            Bs[nb][cA + 2][rA] = pb.z; Bs[nb][cA + 3][rA] = pb.w;
        }
        __syncthreads();
        buf ^= 1;
    }

    // epilogue: per-row L2 norm across the 64-wide head segment
    #pragma unroll
    for (int i = 0; i < 8; i++) {
        float2 c01 = upk(acc[i][0]);
        float2 c23 = upk(acc[i][1]);
        float ss = c01.x * c01.x + c01.y * c01.y + c23.x * c23.x + c23.y * c23.y;
        #pragma unroll
        for (int o = 8; o >= 1; o >>= 1)
            ss += __shfl_xor_sync(0xffffffffu, ss, o);
        float inv = 1.0f / fmaxf(sqrtf(ss), 1e-12f);
        int m = m0 + msub + i;
        int b = m & 15, s = m >> 4;
        float4 r;
        r.x = c01.x * inv; r.y = c01.y * inv; r.z = c23.x * inv; r.w = c23.y * inv;
        *(float4*)&dst[(((size_t)(b * HH + h)) * SS + s) * KK + nsub] = r;
    }
}

// ---------------------------------------------------------------------------
// Kernel 2: streaming attention, 128(q) x 64(t) tiles, no-max softmax.
// 256 threads, 8x4 per-thread fragments in both GEMMs, f32x2 FMAs.
// Dynamic smem: Qs[64][132] + Ks[64][68] + Vs[64][68] + Ps[128][68].
// ---------------------------------------------------------------------------
#define Q_STRIDE 132
#define K_STRIDE 68
#define ATT_SMEM_FLOATS (64 * Q_STRIDE + 64 * K_STRIDE + 64 * K_STRIDE + 128 * K_STRIDE)

__global__ __launch_bounds__(256, 2) void attn_kernel()
{
    extern __shared__ __align__(16) float smem[];
    float* Qs = smem;                                  // [d][m]  64 x 132
    float* Ks = Qs + 64 * Q_STRIDE;                    // [d][t]  64 x 68
    float* Vs = Ks + 64 * K_STRIDE;                    // [t][kd] 64 x 68
    float* Ps = Vs + 64 * K_STRIDE;                    // [m][t] 128 x 68

    const int s0 = blockIdx.x * 128;
    const int bh = blockIdx.y;

    const float* Qp = g_wq + (size_t)bh * SS * KK;
    const float* Kp = g_wk + (size_t)bh * SS * KK;
    const float* Vp = g_wv + (size_t)bh * SS * KK;

    const int tid  = threadIdx.x;
    const int tx   = tid & 15, ty = tid >> 4;
    const int msub = ty * 8, tsub = tx * 4;

    // load Q tile, transposed Qs[d][m]
    #pragma unroll
    for (int it = 0; it < 8; it++) {
        int i = tid + it * 256;            // 0..2047
        int m = i >> 4, c4 = (i & 15) * 4;
        float4 qv = *(const float4*)&Qp[(size_t)(s0 + m) * KK + c4];
        Qs[(c4 + 0) * Q_STRIDE + m] = qv.x;
        Qs[(c4 + 1) * Q_STRIDE + m] = qv.y;
        Qs[(c4 + 2) * Q_STRIDE + m] = qv.z;
        Qs[(c4 + 3) * Q_STRIDE + m] = qv.w;
    }

    ull o[8][2] = {};
    float lacc[8] = {};

    for (int t0 = 0; t0 < SS; t0 += 64) {
        __syncthreads();   // prior tile's Ks/Vs/Ps consumers done (covers Qs on iter 0)
        #pragma unroll
        for (int it = 0; it < 4; it++) {
            int i = tid + it * 256;        // 0..1023
            int r = i >> 4, c4 = (i & 15) * 4;
            float4 kv = *(const float4*)&Kp[(size_t)(t0 + r) * KK + c4];
            Ks[(c4 + 0) * K_STRIDE + r] = kv.x;
            Ks[(c4 + 1) * K_STRIDE + r] = kv.y;
            Ks[(c4 + 2) * K_STRIDE + r] = kv.z;
            Ks[(c4 + 3) * K_STRIDE + r] = kv.w;
            float4 vv = *(const float4*)&Vp[(size_t)(t0 + r) * KK + c4];
            *(float4*)&Vs[r * K_STRIDE + c4] = vv;
        }
        __syncthreads();

        // scores: sc[m 8][t 4] += Q[m][d] * K[t][d]
        ull sc[8][2] = {};
        #pragma unroll 16
        for (int d = 0; d < 64; d++) {
            float4 A0 = *(const float4*)&Qs[d * Q_STRIDE + msub];
            float4 A1 = *(const float4*)&Qs[d * Q_STRIDE + msub + 4];
            ulonglong2 Kv = *(const ulonglong2*)&Ks[d * K_STRIDE + tsub];
            float av[8] = {A0.x, A0.y, A0.z, A0.w, A1.x, A1.y, A1.z, A1.w};
            #pragma unroll
            for (int i = 0; i < 8; i++) {
                ull dd = pk2(av[i], av[i]);
                fma2(sc[i][0], dd, Kv.x);
                fma2(sc[i][1], dd, Kv.y);
            }
        }

        // exp (scores bounded: |sc/8| <= 1/8 -> no running max), store P, row sums
        #pragma unroll
        for (int i = 0; i < 8; i++) {
            float2 e01 = upk(sc[i][0]);
            float2 e23 = upk(sc[i][1]);
            float4 ev;
            ev.x = __expf(e01.x * 0.125f);
            ev.y = __expf(e01.y * 0.125f);
            ev.z = __expf(e23.x * 0.125f);
            ev.w = __expf(e23.y * 0.125f);
            lacc[i] += ev.x + ev.y + ev.z + ev.w;
            *(float4*)&Ps[(msub + i) * K_STRIDE + tsub] = ev;
        }
        __syncthreads();

        // O[m][kd] += P[m][t] * V[t][kd]
        #pragma unroll 8
        for (int tt = 0; tt < 64; tt++) {
            ulonglong2 Vv = *(const ulonglong2*)&Vs[tt * K_STRIDE + tsub];
            #pragma unroll
            for (int i = 0; i < 8; i++) {
                float p = Ps[(msub + i) * K_STRIDE + tt];
                ull dd = pk2(p, p);
                fma2(o[i][0], dd, Vv.x);
                fma2(o[i][1], dd, Vv.y);
            }
        }
    }

    // normalize rows, write out
    #pragma unroll
    for (int i = 0; i < 8; i++) {
        float ss = lacc[i];
        #pragma unroll
        for (int of = 8; of >= 1; of >>= 1)
            ss += __shfl_xor_sync(0xffffffffu, ss, of);
        float inv = 1.0f / ss;
        float2 c01 = upk(o[i][0]);
        float2 c23 = upk(o[i][1]);
        float4 r;
        r.x = c01.x * inv; r.y = c01.y * inv; r.z = c23.x * inv; r.w = c23.y * inv;
        *(float4*)&g_att[((size_t)bh * SS + s0 + msub + i) * KK + tsub] = r;
    }
}

// ---------------------------------------------------------------------------
// Kernel 3: output projection GEMM.  out[m][d] = sum_j concat[m][j] Wout[d][j]
// M=16384, N=512, inner=512. Same 128x64/kc16 f32x2 template as kernel 1.
// ---------------------------------------------------------------------------
__global__ __launch_bounds__(256) void outproj_kernel(
    const float* __restrict__ Wout, float* __restrict__ out)
{
    const int n0 = blockIdx.x * 64;        // d offset
    const int m0 = blockIdx.y * 128;

    __shared__ __align__(16) float As[2][16][132];
    __shared__ __align__(16) float Bs[2][16][68];

    const int tid  = threadIdx.x;
    const int tx   = tid & 15, ty = tid >> 4;
    const int msub = ty * 8, nsub = tx * 4;

    const int rA = tid >> 2;
    const int cA = (tid & 3) * 4;
    // per-loader-row decomposition of m for g_att gather
    const int mA0 = m0 + rA,      bA0 = mA0 & 15, sA0 = mA0 >> 4;
    const int mA1 = m0 + rA + 64, bA1 = mA1 & 15, sA1 = mA1 >> 4;

    ull acc[8][2] = {};

    auto ldA = [&](int b, int s, int j) -> float4 {
        int h = j >> 6;
        return *(const float4*)&g_att[(((size_t)(b * HH + h)) * SS + s) * KK + (j & 63)];
    };

    // preload tile 0
    {
        float4 a0 = ldA(bA0, sA0, cA);
        float4 a1 = ldA(bA1, sA1, cA);
        float4 b0 = *(const float4*)&Wout[(size_t)(n0 + rA) * (HH * KK) + cA];
        As[0][cA + 0][rA] = a0.x; As[0][cA + 1][rA] = a0.y;
        As[0][cA + 2][rA] = a0.z; As[0][cA + 3][rA] = a0.w;
        As[0][cA + 0][rA + 64] = a1.x; As[0][cA + 1][rA + 64] = a1.y;
        As[0][cA + 2][rA + 64] = a1.z; As[0][cA + 3][rA + 64] = a1.w;
        Bs[0][cA + 0][rA] = b0.x; Bs[0][cA + 1][rA] = b0.y;
        Bs[0][cA + 2][rA] = b0.z; Bs[0][cA + 3][rA] = b0.w;
    }
    __syncthreads();

    int buf = 0;
    for (int j0 = 0; j0 < HH * KK; j0 += 16) {
        const bool has_next = (j0 + 16) < HH * KK;
        float4 pa0, pa1, pb;
        if (has_next) {
            pa0 = ldA(bA0, sA0, j0 + 16 + cA);
            pa1 = ldA(bA1, sA1, j0 + 16 + cA);
            pb  = *(const float4*)&Wout[(size_t)(n0 + rA) * (HH * KK) + j0 + 16 + cA];
        }
        #pragma unroll
        for (int k = 0; k < 16; k++) {
            float4 A0 = *(const float4*)&As[buf][k][msub];
            float4 A1 = *(const float4*)&As[buf][k][msub + 4];
            ulonglong2 Wv = *(const ulonglong2*)&Bs[buf][k][nsub];
            float av[8] = {A0.x, A0.y, A0.z, A0.w, A1.x, A1.y, A1.z, A1.w};
            #pragma unroll
            for (int i = 0; i < 8; i++) {
                ull d = pk2(av[i], av[i]);
                fma2(acc[i][0], d, Wv.x);
                fma2(acc[i][1], d, Wv.y);
            }
        }
        if (has_next) {
            int nb = buf ^ 1;
            As[nb][cA + 0][rA] = pa0.x; As[nb][cA + 1][rA] = pa0.y;
            As[nb][cA + 2][rA] = pa0.z; As[nb][cA + 3][rA] = pa0.w;
            As[nb][cA + 0][rA + 64] = pa1.x; As[nb][cA + 1][rA + 64] = pa1.y;
            As[nb][cA + 2][rA + 64] = pa1.z; As[nb][cA + 3][rA + 64] = pa1.w;
            Bs[nb][cA + 0][rA] = pb.x; Bs[nb][cA + 1][rA] = pb.y;
            Bs[nb][cA + 2][rA] = pb.z; Bs[nb][cA + 3][rA] = pb.w;
        }
        __syncthreads();
        buf ^= 1;
    }

    #pragma unroll
    for (int i = 0; i < 8; i++) {
        int m = m0 + msub + i;
        float2 c01 = upk(acc[i][0]);
        float2 c23 = upk(acc[i][1]);
        float4 r; r.x = c01.x; r.y = c01.y; r.z = c23.x; r.w = c23.y;
        *(float4*)&out[(size_t)m * DD + n0 + nsub] = r;
    }
}

// ---------------------------------------------------------------------------
extern "C" void kernel_launch(void* const* d_in, const int* in_sizes, int n_in,
                              void* d_out, int out_size)
{
    const float* q    = (const float*)d_in[0];
    const float* k    = (const float*)d_in[1];
    const float* v    = (const float*)d_in[2];
    const float* WQ   = (const float*)d_in[3];
    const float* WK   = (const float*)d_in[4];
    const float* WV   = (const float*)d_in[5];
    const float* Wout = (const float*)d_in[6];
    float* out = (float*)d_out;

    const int attn_smem = ATT_SMEM_FLOATS * (int)sizeof(float);  // 103424 B
    cudaFuncSetAttribute(attn_kernel,
                         cudaFuncAttributeMaxDynamicSharedMemorySize, attn_smem);

    proj_norm_kernel<<<dim3(24, 128), 256>>>(q, k, v, WQ, WK, WV);
    attn_kernel<<<dim3(SS / 128, BB * HH), 256, attn_smem>>>();
    outproj_kernel<<<dim3(8, 128), 256>>>(Wout, out);
}

// round 6
// speedup vs baseline: 2.3136x; 1.2776x over previous
#include <cuda_runtime.h>
#include <cuda_bf16.h>
#include <math.h>
#include <stdint.h>

#define SS 1024
#define BB 16
#define DD 512
#define HH 8
#define KK 64

using ull = unsigned long long;

// fp32 normalized projections (consumed by SIMT attention)
__device__ float g_wq[BB * HH * SS * KK];
__device__ float g_wk[BB * HH * SS * KK];
__device__ float g_wv[BB * HH * SS * KK];
// bf16 hi/lo splits
__device__ __nv_bfloat16 g_ih[3 * SS * BB * DD];   // q,k,v inputs [t][m=s*16+b][d]
__device__ __nv_bfloat16 g_il[3 * SS * BB * DD];
__device__ __nv_bfloat16 g_wh[3 * DD * DD];        // WQ,WK,WV [t][n][d]
__device__ __nv_bfloat16 g_wl[3 * DD * DD];
__device__ __nv_bfloat16 g_oh[DD * DD];            // Wout [n][j]
__device__ __nv_bfloat16 g_ol[DD * DD];
__device__ __nv_bfloat16 g_ath[SS * BB * HH * KK]; // attention out [m][j]
__device__ __nv_bfloat16 g_atl[SS * BB * HH * KK];

// ---------------------------------------------------------------------------
// helpers
// ---------------------------------------------------------------------------
__device__ __forceinline__ uint32_t smem_u32(const void* p) {
    uint32_t a;
    asm("{ .reg .u64 t; cvta.to.shared.u64 t, %1; cvt.u32.u64 %0, t; }"
        : "=r"(a) : "l"(p));
    return a;
}

__device__ __forceinline__ unsigned bpack(float lo_elem, float hi_elem) {
    unsigned r;  // lower 16 = bf16(lo_elem), upper 16 = bf16(hi_elem)
    asm("cvt.rn.bf16x2.f32 %0, %1, %2;" : "=r"(r) : "f"(hi_elem), "f"(lo_elem));
    return r;
}
__device__ __forceinline__ void split2(float x, float y, unsigned& hi, unsigned& lo) {
    unsigned h = bpack(x, y);
    float hx = __uint_as_float(h << 16);
    float hy = __uint_as_float(h & 0xffff0000u);
    hi = h;
    lo = bpack(x - hx, y - hy);
}

__device__ __forceinline__ void ldsm4(unsigned* r, uint32_t addr) {
    asm volatile("ldmatrix.sync.aligned.m8n8.x4.shared.b16 {%0,%1,%2,%3}, [%4];"
                 : "=r"(r[0]), "=r"(r[1]), "=r"(r[2]), "=r"(r[3]) : "r"(addr));
}
__device__ __forceinline__ void mma16816(float* d, const unsigned* a, const unsigned* b) {
    asm volatile("mma.sync.aligned.m16n8k16.row.col.f32.bf16.bf16.f32 "
                 "{%0,%1,%2,%3}, {%4,%5,%6,%7}, {%8,%9}, {%0,%1,%2,%3};"
                 : "+f"(d[0]), "+f"(d[1]), "+f"(d[2]), "+f"(d[3])
                 : "r"(a[0]), "r"(a[1]), "r"(a[2]), "r"(a[3]), "r"(b[0]), "r"(b[1]));
}
__device__ __forceinline__ void cpasync16(uint32_t saddr, const void* gaddr) {
    asm volatile("cp.async.ca.shared.global [%0], [%1], 16;"
                 :: "r"(saddr), "l"(gaddr) : "memory");
}
#define CP_COMMIT() asm volatile("cp.async.commit_group;" ::: "memory")
#define CP_WAIT(n)  asm volatile("cp.async.wait_group %0;" :: "n"(n) : "memory")

// smem tile layout (per stage): rows padded to 80B (40 bf16) -> ldmatrix conflict-free
#define ROW_B   80
#define ARR_B   10240            // 128 rows * 80B
#define A_HI    0
#define A_LO    10240
#define B_HI    20480
#define B_LO    30720
#define STAGE_B 40960
#define MMA_SMEM (2 * STAGE_B)

// ---------------------------------------------------------------------------
// convert: fp32 -> bf16 hi/lo split (grid-stride over float4)
// ---------------------------------------------------------------------------
__global__ void cvt_split(const float4* __restrict__ src, uint2* __restrict__ hi,
                          uint2* __restrict__ lo, int n4)
{
    for (int i = blockIdx.x * blockDim.x + threadIdx.x; i < n4;
         i += gridDim.x * blockDim.x) {
        float4 x = src[i];
        unsigned h0, l0, h1, l1;
        split2(x.x, x.y, h0, l0);
        split2(x.z, x.w, h1, l1);
        hi[i] = make_uint2(h0, h1);
        lo[i] = make_uint2(l0, l1);
    }
}

// ---------------------------------------------------------------------------
// shared mma mainloop body: computes 128x128 fp32 tile into d[2][8][4].
// srcA/srcB point at the tile's first row ([row][512] bf16, row-major).
// ---------------------------------------------------------------------------
struct MmaCtx {
    float d[2][8][4];
    uint32_t aHi[2], aLo[2], bHi[4], bLo[4];   // per-lane ldmatrix base addrs
};

__device__ __forceinline__ void mma_mainloop(
    MmaCtx& cx, uint32_t sb,
    const __nv_bfloat16* srcAh, const __nv_bfloat16* srcAl,
    const __nv_bfloat16* srcBh, const __nv_bfloat16* srcBl)
{
    const int tid = threadIdx.x;
    const int wid = tid >> 5, lane = tid & 31;
    const int wm = (wid & 3) * 32, wn = (wid >> 2) * 64;

    // ldmatrix per-lane base addresses (stage/ks offsets added later)
    #pragma unroll
    for (int mb = 0; mb < 2; mb++) {
        uint32_t ro = (uint32_t)(wm + mb * 16 + (lane & 15)) * ROW_B + (lane >> 4) * 16;
        cx.aHi[mb] = sb + A_HI + ro;
        cx.aLo[mb] = sb + A_LO + ro;
    }
    #pragma unroll
    for (int p = 0; p < 4; p++) {
        uint32_t ro = (uint32_t)(wn + p * 16 + (lane >> 4) * 8 + (lane & 7)) * ROW_B
                    + ((lane >> 3) & 1) * 16;
        cx.bHi[p] = sb + B_HI + ro;
        cx.bLo[p] = sb + B_LO + ro;
    }
    #pragma unroll
    for (int mb = 0; mb < 2; mb++)
        #pragma unroll
        for (int nb = 0; nb < 8; nb++)
            #pragma unroll
            for (int e = 0; e < 4; e++) cx.d[mb][nb][e] = 0.f;

    // cp.async chunk coords for this thread: 8 chunks/stage
    const int arr = tid >> 5 & 0 ; (void)arr;

    // prefetch stage 0
    {
        #pragma unroll
        for (int i = 0; i < 8; i++) {
            int idx = tid + i * 256;
            int a = idx >> 9, ci = idx & 511, r = ci >> 2, cc = ci & 3;
            const __nv_bfloat16* s =
                (a == 0) ? srcAh : (a == 1) ? srcAl : (a == 2) ? srcBh : srcBl;
            cpasync16(sb + a * ARR_B + (uint32_t)(r * ROW_B + cc * 16),
                      s + (size_t)r * DD + cc * 8);
        }
        CP_COMMIT();
    }

    for (int it = 0; it < 16; it++) {
        if (it + 1 < 16) {
            uint32_t stb = sb + (uint32_t)((it + 1) & 1) * STAGE_B;
            int k0 = (it + 1) * 32;
            #pragma unroll
            for (int i = 0; i < 8; i++) {
                int idx = tid + i * 256;
                int a = idx >> 9, ci = idx & 511, r = ci >> 2, cc = ci & 3;
                const __nv_bfloat16* s =
                    (a == 0) ? srcAh : (a == 1) ? srcAl : (a == 2) ? srcBh : srcBl;
                cpasync16(stb + a * ARR_B + (uint32_t)(r * ROW_B + cc * 16),
                          s + (size_t)r * DD + k0 + cc * 8);
            }
            CP_COMMIT();
            CP_WAIT(1);
        } else {
            CP_WAIT(0);
        }
        __syncthreads();

        const uint32_t so = (uint32_t)(it & 1) * STAGE_B;
        #pragma unroll
        for (int ks = 0; ks < 2; ks++) {
            const uint32_t off = so + ks * 32;
            unsigned ah[2][4], al[2][4];
            #pragma unroll
            for (int mb = 0; mb < 2; mb++) {
                ldsm4(ah[mb], cx.aHi[mb] + off);
                ldsm4(al[mb], cx.aLo[mb] + off);
            }
            #pragma unroll
            for (int p = 0; p < 4; p++) {
                unsigned tbh[4], tbl[4];
                ldsm4(tbh, cx.bHi[p] + off);
                ldsm4(tbl, cx.bLo[p] + off);
                #pragma unroll
                for (int mb = 0; mb < 2; mb++)
                    #pragma unroll
                    for (int qn = 0; qn < 2; qn++) {
                        int nb = 2 * p + qn;
                        mma16816(cx.d[mb][nb], ah[mb], &tbh[2 * qn]);
                        mma16816(cx.d[mb][nb], ah[mb], &tbl[2 * qn]);
                        mma16816(cx.d[mb][nb], al[mb], &tbh[2 * qn]);
                    }
            }
        }
        __syncthreads();
    }
}

// ---------------------------------------------------------------------------
// Kernel: projection + L2 norm.  grid (12, 128): x -> n0 = x*128 (t = n0/512),
// y -> m0 = y*128. Writes fp32 g_wq/g_wk/g_wv in [b,h,s,k] layout.
// ---------------------------------------------------------------------------
__global__ __launch_bounds__(256) void proj_mma()
{
    extern __shared__ __align__(16) char dsm[];
    const uint32_t sb = smem_u32(dsm);

    const int n0 = blockIdx.x * 128;
    const int m0 = blockIdx.y * 128;
    const int t  = n0 >> 9;
    const int nr = n0 & 511;

    const __nv_bfloat16* srcAh = g_ih + (size_t)t * (SS * BB * DD) + (size_t)m0 * DD;
    const __nv_bfloat16* srcAl = g_il + (size_t)t * (SS * BB * DD) + (size_t)m0 * DD;
    const __nv_bfloat16* srcBh = g_wh + (size_t)t * (DD * DD) + (size_t)nr * DD;
    const __nv_bfloat16* srcBl = g_wl + (size_t)t * (DD * DD) + (size_t)nr * DD;
    float* dst = (t == 0) ? g_wq : (t == 1) ? g_wk : g_wv;

    MmaCtx cx;
    mma_mainloop(cx, sb, srcAh, srcAl, srcBh, srcBl);

    // epilogue: row L2-norm per 64-col head, scatter to [b,h,s,k]
    const int tid = threadIdx.x;
    const int wid = tid >> 5, lane = tid & 31;
    const int wm = (wid & 3) * 32, wn = (wid >> 2) * 64;
    const int r0 = lane >> 2, c0 = lane & 3;
    const int h = (nr >> 6) + (wn >> 6);

    #pragma unroll
    for (int mb = 0; mb < 2; mb++) {
        float ssa = 0.f, ssb = 0.f;
        #pragma unroll
        for (int nb = 0; nb < 8; nb++) {
            float* d = cx.d[mb][nb];
            ssa = fmaf(d[0], d[0], fmaf(d[1], d[1], ssa));
            ssb = fmaf(d[2], d[2], fmaf(d[3], d[3], ssb));
        }
        ssa += __shfl_xor_sync(0xffffffffu, ssa, 1);
        ssa += __shfl_xor_sync(0xffffffffu, ssa, 2);
        ssb += __shfl_xor_sync(0xffffffffu, ssb, 1);
        ssb += __shfl_xor_sync(0xffffffffu, ssb, 2);
        float inva = 1.0f / fmaxf(sqrtf(ssa), 1e-12f);
        float invb = 1.0f / fmaxf(sqrtf(ssb), 1e-12f);

        int ma = m0 + wm + mb * 16 + r0;
        int mb2 = ma + 8;
        int ba = ma & 15, sa = ma >> 4;
        int bbb = mb2 & 15, sbb = mb2 >> 4;
        float* pa = dst + (((size_t)(ba * HH + h)) * SS + sa) * KK;
        float* pb = dst + (((size_t)(bbb * HH + h)) * SS + sbb) * KK;
        #pragma unroll
        for (int nb = 0; nb < 8; nb++) {
            int kk = ((wn & 63) + nb * 8 + 2 * c0);
            float* d = cx.d[mb][nb];
            *(float2*)&pa[kk] = make_float2(d[0] * inva, d[1] * inva);
            *(float2*)&pb[kk] = make_float2(d[2] * invb, d[3] * invb);
        }
    }
}

// ---------------------------------------------------------------------------
// Kernel: output projection.  grid (4, 128). out[m][n] fp32.
// ---------------------------------------------------------------------------
__global__ __launch_bounds__(256) void outproj_mma(float* __restrict__ out)
{
    extern __shared__ __align__(16) char dsm[];
    const uint32_t sb = smem_u32(dsm);

    const int n0 = blockIdx.x * 128;
    const int m0 = blockIdx.y * 128;

    const __nv_bfloat16* srcAh = g_ath + (size_t)m0 * DD;
    const __nv_bfloat16* srcAl = g_atl + (size_t)m0 * DD;
    const __nv_bfloat16* srcBh = g_oh + (size_t)n0 * DD;
    const __nv_bfloat16* srcBl = g_ol + (size_t)n0 * DD;

    MmaCtx cx;
    mma_mainloop(cx, sb, srcAh, srcAl, srcBh, srcBl);

    const int tid = threadIdx.x;
    const int wid = tid >> 5, lane = tid & 31;
    const int wm = (wid & 3) * 32, wn = (wid >> 2) * 64;
    const int r0 = lane >> 2, c0 = lane & 3;

    #pragma unroll
    for (int mb = 0; mb < 2; mb++) {
        int ma = m0 + wm + mb * 16 + r0;
        float* pa = out + (size_t)ma * DD;
        float* pb = out + (size_t)(ma + 8) * DD;
        #pragma unroll
        for (int nb = 0; nb < 8; nb++) {
            int n = n0 + wn + nb * 8 + 2 * c0;
            float* d = cx.d[mb][nb];
            *(float2*)&pa[n] = make_float2(d[0], d[1]);
            *(float2*)&pb[n] = make_float2(d[2], d[3]);
        }
    }
}

// ---------------------------------------------------------------------------
// Kernel 2: SIMT streaming attention (f32x2), epilogue -> bf16 hi/lo [m][j].
// ---------------------------------------------------------------------------
__device__ __forceinline__ ull pk2(float x, float y) {
    ull r; asm("mov.b64 %0, {%1, %2};" : "=l"(r) : "f"(x), "f"(y)); return r;
}
__device__ __forceinline__ void fma2(ull& d, ull a, ull b) {
    asm("fma.rn.f32x2 %0, %1, %2, %0;" : "+l"(d) : "l"(a), "l"(b));
}
__device__ __forceinline__ float2 upk(ull a) {
    float2 f; asm("mov.b64 {%0, %1}, %2;" : "=f"(f.x), "=f"(f.y) : "l"(a)); return f;
}

#define Q_STRIDE 132
#define K_STRIDE 68
#define ATT_SMEM_FLOATS (64 * Q_STRIDE + 64 * K_STRIDE + 64 * K_STRIDE + 128 * K_STRIDE)

__global__ __launch_bounds__(256, 2) void attn_kernel()
{
    extern __shared__ __align__(16) float smem[];
    float* Qs = smem;
    float* Ks = Qs + 64 * Q_STRIDE;
    float* Vs = Ks + 64 * K_STRIDE;
    float* Ps = Vs + 64 * K_STRIDE;

    const int s0 = blockIdx.x * 128;
    const int bh = blockIdx.y;

    const float* Qp = g_wq + (size_t)bh * SS * KK;
    const float* Kp = g_wk + (size_t)bh * SS * KK;
    const float* Vp = g_wv + (size_t)bh * SS * KK;

    const int tid  = threadIdx.x;
    const int tx   = tid & 15, ty = tid >> 4;
    const int msub = ty * 8, tsub = tx * 4;

    #pragma unroll
    for (int it = 0; it < 8; it++) {
        int i = tid + it * 256;
        int m = i >> 4, c4 = (i & 15) * 4;
        float4 qv = *(const float4*)&Qp[(size_t)(s0 + m) * KK + c4];
        Qs[(c4 + 0) * Q_STRIDE + m] = qv.x;
        Qs[(c4 + 1) * Q_STRIDE + m] = qv.y;
        Qs[(c4 + 2) * Q_STRIDE + m] = qv.z;
        Qs[(c4 + 3) * Q_STRIDE + m] = qv.w;
    }

    ull o[8][2] = {};
    float lacc[8] = {};

    for (int t0 = 0; t0 < SS; t0 += 64) {
        __syncthreads();
        #pragma unroll
        for (int it = 0; it < 4; it++) {
            int i = tid + it * 256;
            int r = i >> 4, c4 = (i & 15) * 4;
            float4 kv = *(const float4*)&Kp[(size_t)(t0 + r) * KK + c4];
            Ks[(c4 + 0) * K_STRIDE + r] = kv.x;
            Ks[(c4 + 1) * K_STRIDE + r] = kv.y;
            Ks[(c4 + 2) * K_STRIDE + r] = kv.z;
            Ks[(c4 + 3) * K_STRIDE + r] = kv.w;
            float4 vv = *(const float4*)&Vp[(size_t)(t0 + r) * KK + c4];
            *(float4*)&Vs[r * K_STRIDE + c4] = vv;
        }
        __syncthreads();

        ull sc[8][2] = {};
        #pragma unroll 16
        for (int d = 0; d < 64; d++) {
            float4 A0 = *(const float4*)&Qs[d * Q_STRIDE + msub];
            float4 A1 = *(const float4*)&Qs[d * Q_STRIDE + msub + 4];
            ulonglong2 Kv = *(const ulonglong2*)&Ks[d * K_STRIDE + tsub];
            float av[8] = {A0.x, A0.y, A0.z, A0.w, A1.x, A1.y, A1.z, A1.w};
            #pragma unroll
            for (int i = 0; i < 8; i++) {
                ull dd = pk2(av[i], av[i]);
                fma2(sc[i][0], dd, Kv.x);
                fma2(sc[i][1], dd, Kv.y);
            }
        }

        #pragma unroll
        for (int i = 0; i < 8; i++) {
            float2 e01 = upk(sc[i][0]);
            float2 e23 = upk(sc[i][1]);
            float4 ev;
            ev.x = __expf(e01.x * 0.125f);
            ev.y = __expf(e01.y * 0.125f);
            ev.z = __expf(e23.x * 0.125f);
            ev.w = __expf(e23.y * 0.125f);
            lacc[i] += ev.x + ev.y + ev.z + ev.w;
            *(float4*)&Ps[(msub + i) * K_STRIDE + tsub] = ev;
        }
        __syncthreads();

        #pragma unroll 8
        for (int tt = 0; tt < 64; tt++) {
            ulonglong2 Vv = *(const ulonglong2*)&Vs[tt * K_STRIDE + tsub];
            #pragma unroll
            for (int i = 0; i < 8; i++) {
                float p = Ps[(msub + i) * K_STRIDE + tt];
                ull dd = pk2(p, p);
                fma2(o[i][0], dd, Vv.x);
                fma2(o[i][1], dd, Vv.y);
            }
        }
    }

    const int b = bh >> 3, h = bh & 7;
    #pragma unroll
    for (int i = 0; i < 8; i++) {
        float ss = lacc[i];
        #pragma unroll
        for (int of = 8; of >= 1; of >>= 1)
            ss += __shfl_xor_sync(0xffffffffu, ss, of);
        float inv = 1.0f / ss;
        float2 c01 = upk(o[i][0]);
        float2 c23 = upk(o[i][1]);
        float4 r;
        r.x = c01.x * inv; r.y = c01.y * inv; r.z = c23.x * inv; r.w = c23.y * inv;
        unsigned h0, l0, h1, l1;
        split2(r.x, r.y, h0, l0);
        split2(r.z, r.w, h1, l1);
        size_t m = (size_t)(s0 + msub + i) * BB + b;
        size_t j = (size_t)h * KK + tsub;
        *(uint2*)&g_ath[m * (HH * KK) + j] = make_uint2(h0, h1);
        *(uint2*)&g_atl[m * (HH * KK) + j] = make_uint2(l0, l1);
    }
}

// ---------------------------------------------------------------------------
extern "C" void kernel_launch(void* const* d_in, const int* in_sizes, int n_in,
                              void* d_out, int out_size)
{
    const float* q    = (const float*)d_in[0];
    const float* k    = (const float*)d_in[1];
    const float* v    = (const float*)d_in[2];
    const float* WQ   = (const float*)d_in[3];
    const float* WK   = (const float*)d_in[4];
    const float* WV   = (const float*)d_in[5];
    const float* Wout = (const float*)d_in[6];
    float* out = (float*)d_out;

    const int attn_smem = ATT_SMEM_FLOATS * (int)sizeof(float);
    cudaFuncSetAttribute(attn_kernel,
                         cudaFuncAttributeMaxDynamicSharedMemorySize, attn_smem);
    cudaFuncSetAttribute(proj_mma,
                         cudaFuncAttributeMaxDynamicSharedMemorySize, MMA_SMEM);
    cudaFuncSetAttribute(outproj_mma,
                         cudaFuncAttributeMaxDynamicSharedMemorySize, MMA_SMEM);

    // device pointers to static arrays
    __nv_bfloat16 *ih, *il, *wh, *wl, *oh, *ol;
    cudaGetSymbolAddress((void**)&ih, g_ih);
    cudaGetSymbolAddress((void**)&il, g_il);
    cudaGetSymbolAddress((void**)&wh, g_wh);
    cudaGetSymbolAddress((void**)&wl, g_wl);
    cudaGetSymbolAddress((void**)&oh, g_oh);
    cudaGetSymbolAddress((void**)&ol, g_ol);

    const int nIn4 = SS * BB * DD / 4;       // 2,097,152
    const int nW4  = DD * DD / 4;            // 65,536
    cvt_split<<<2048, 256>>>((const float4*)q, (uint2*)ih, (uint2*)il, nIn4);
    cvt_split<<<2048, 256>>>((const float4*)k, (uint2*)(ih + SS * BB * DD),
                             (uint2*)(il + SS * BB * DD), nIn4);
    cvt_split<<<2048, 256>>>((const float4*)v, (uint2*)(ih + 2 * SS * BB * DD),
                             (uint2*)(il + 2 * SS * BB * DD), nIn4);
    cvt_split<<<256, 256>>>((const float4*)WQ, (uint2*)wh, (uint2*)wl, nW4);
    cvt_split<<<256, 256>>>((const float4*)WK, (uint2*)(wh + DD * DD),
                            (uint2*)(wl + DD * DD), nW4);
    cvt_split<<<256, 256>>>((const float4*)WV, (uint2*)(wh + 2 * DD * DD),
                            (uint2*)(wl + 2 * DD * DD), nW4);
    cvt_split<<<256, 256>>>((const float4*)Wout, (uint2*)oh, (uint2*)ol, nW4);

    proj_mma<<<dim3(12, 128), 256, MMA_SMEM>>>();
    attn_kernel<<<dim3(SS / 128, BB * HH), 256, attn_smem>>>();
    outproj_mma<<<dim3(4, 128), 256, MMA_SMEM>>>(out);
}

// round 7
// speedup vs baseline: 4.4645x; 1.9297x over previous
#include <cuda_runtime.h>
#include <cuda_bf16.h>
#include <math.h>
#include <stdint.h>

#define SS 1024
#define BB 16
#define DD 512
#define HH 8
#define KK 64

using ull = unsigned long long;

// bf16 hi/lo splits of inputs & weights (for proj / outproj GEMMs)
__device__ __nv_bfloat16 g_ih[3 * SS * BB * DD];   // q,k,v inputs [t][m=s*16+b][d]
__device__ __nv_bfloat16 g_il[3 * SS * BB * DD];
__device__ __nv_bfloat16 g_wh[3 * DD * DD];        // WQ,WK,WV [t][n][d]
__device__ __nv_bfloat16 g_wl[3 * DD * DD];
__device__ __nv_bfloat16 g_oh[DD * DD];            // Wout [n][j]
__device__ __nv_bfloat16 g_ol[DD * DD];
// normalized projections, bf16 hi/lo, [bh][s][k]
__device__ __nv_bfloat16 g_qh[BB * HH * SS * KK];
__device__ __nv_bfloat16 g_kh[BB * HH * SS * KK];
__device__ __nv_bfloat16 g_kl[BB * HH * SS * KK];
__device__ __nv_bfloat16 g_vh[BB * HH * SS * KK];
__device__ __nv_bfloat16 g_vl[BB * HH * SS * KK];
// attention output [m = s*16+b][j = h*64+k], bf16 hi/lo
__device__ __nv_bfloat16 g_ath[SS * BB * HH * KK];
__device__ __nv_bfloat16 g_atl[SS * BB * HH * KK];

// ---------------------------------------------------------------------------
// helpers
// ---------------------------------------------------------------------------
__device__ __forceinline__ uint32_t smem_u32(const void* p) {
    uint32_t a;
    asm("{ .reg .u64 t; cvta.to.shared.u64 t, %1; cvt.u32.u64 %0, t; }"
        : "=r"(a) : "l"(p));
    return a;
}

__device__ __forceinline__ unsigned bpack(float lo_elem, float hi_elem) {
    unsigned r;  // lower 16 = bf16(lo_elem), upper 16 = bf16(hi_elem)
    asm("cvt.rn.bf16x2.f32 %0, %1, %2;" : "=r"(r) : "f"(hi_elem), "f"(lo_elem));
    return r;
}
__device__ __forceinline__ void split2(float x, float y, unsigned& hi, unsigned& lo) {
    unsigned h = bpack(x, y);
    float hx = __uint_as_float(h << 16);
    float hy = __uint_as_float(h & 0xffff0000u);
    hi = h;
    lo = bpack(x - hx, y - hy);
}

__device__ __forceinline__ void ldsm4(unsigned* r, uint32_t addr) {
    asm volatile("ldmatrix.sync.aligned.m8n8.x4.shared.b16 {%0,%1,%2,%3}, [%4];"
                 : "=r"(r[0]), "=r"(r[1]), "=r"(r[2]), "=r"(r[3]) : "r"(addr));
}
__device__ __forceinline__ void ldsm4t(unsigned* r, uint32_t addr) {
    asm volatile("ldmatrix.sync.aligned.m8n8.x4.trans.shared.b16 {%0,%1,%2,%3}, [%4];"
                 : "=r"(r[0]), "=r"(r[1]), "=r"(r[2]), "=r"(r[3]) : "r"(addr));
}
__device__ __forceinline__ void mma16816(float* d, const unsigned* a, const unsigned* b) {
    asm volatile("mma.sync.aligned.m16n8k16.row.col.f32.bf16.bf16.f32 "
                 "{%0,%1,%2,%3}, {%4,%5,%6,%7}, {%8,%9}, {%0,%1,%2,%3};"
                 : "+f"(d[0]), "+f"(d[1]), "+f"(d[2]), "+f"(d[3])
                 : "r"(a[0]), "r"(a[1]), "r"(a[2]), "r"(a[3]), "r"(b[0]), "r"(b[1]));
}
__device__ __forceinline__ void cpasync16(uint32_t saddr, const void* gaddr) {
    asm volatile("cp.async.ca.shared.global [%0], [%1], 16;"
                 :: "r"(saddr), "l"(gaddr) : "memory");
}
#define CP_COMMIT() asm volatile("cp.async.commit_group;" ::: "memory")
#define CP_WAIT(n)  asm volatile("cp.async.wait_group %0;" :: "n"(n) : "memory")

// GEMM smem layout: rows of 32 bf16 padded to 80B
#define ROW_B   80
#define ARR_B   10240
#define A_HI    0
#define A_LO    10240
#define B_HI    20480
#define B_LO    30720
#define STAGE_B 40960
#define MMA_SMEM (2 * STAGE_B)

// ---------------------------------------------------------------------------
// convert: fp32 -> bf16 hi/lo split
// ---------------------------------------------------------------------------
__global__ void cvt_split(const float4* __restrict__ src, uint2* __restrict__ hi,
                          uint2* __restrict__ lo, int n4)
{
    for (int i = blockIdx.x * blockDim.x + threadIdx.x; i < n4;
         i += gridDim.x * blockDim.x) {
        float4 x = src[i];
        unsigned h0, l0, h1, l1;
        split2(x.x, x.y, h0, l0);
        split2(x.z, x.w, h1, l1);
        hi[i] = make_uint2(h0, h1);
        lo[i] = make_uint2(l0, l1);
    }
}

// ---------------------------------------------------------------------------
// shared mma mainloop: 128x128 fp32 tile in d[2][8][4]
// ---------------------------------------------------------------------------
struct MmaCtx {
    float d[2][8][4];
    uint32_t aHi[2], aLo[2], bHi[4], bLo[4];
};

__device__ __forceinline__ void mma_mainloop(
    MmaCtx& cx, uint32_t sb,
    const __nv_bfloat16* srcAh, const __nv_bfloat16* srcAl,
    const __nv_bfloat16* srcBh, const __nv_bfloat16* srcBl)
{
    const int tid = threadIdx.x;
    const int wid = tid >> 5, lane = tid & 31;
    const int wm = (wid & 3) * 32, wn = (wid >> 2) * 64;

    #pragma unroll
    for (int mb = 0; mb < 2; mb++) {
        uint32_t ro = (uint32_t)(wm + mb * 16 + (lane & 15)) * ROW_B + (lane >> 4) * 16;
        cx.aHi[mb] = sb + A_HI + ro;
        cx.aLo[mb] = sb + A_LO + ro;
    }
    #pragma unroll
    for (int p = 0; p < 4; p++) {
        uint32_t ro = (uint32_t)(wn + p * 16 + (lane >> 4) * 8 + (lane & 7)) * ROW_B
                    + ((lane >> 3) & 1) * 16;
        cx.bHi[p] = sb + B_HI + ro;
        cx.bLo[p] = sb + B_LO + ro;
    }
    #pragma unroll
    for (int mb = 0; mb < 2; mb++)
        #pragma unroll
        for (int nb = 0; nb < 8; nb++)
            #pragma unroll
            for (int e = 0; e < 4; e++) cx.d[mb][nb][e] = 0.f;

    {
        #pragma unroll
        for (int i = 0; i < 8; i++) {
            int idx = tid + i * 256;
            int a = idx >> 9, ci = idx & 511, r = ci >> 2, cc = ci & 3;
            const __nv_bfloat16* s =
                (a == 0) ? srcAh : (a == 1) ? srcAl : (a == 2) ? srcBh : srcBl;
            cpasync16(sb + a * ARR_B + (uint32_t)(r * ROW_B + cc * 16),
                      s + (size_t)r * DD + cc * 8);
        }
        CP_COMMIT();
    }

    for (int it = 0; it < 16; it++) {
        if (it + 1 < 16) {
            uint32_t stb = sb + (uint32_t)((it + 1) & 1) * STAGE_B;
            int k0 = (it + 1) * 32;
            #pragma unroll
            for (int i = 0; i < 8; i++) {
                int idx = tid + i * 256;
                int a = idx >> 9, ci = idx & 511, r = ci >> 2, cc = ci & 3;
                const __nv_bfloat16* s =
                    (a == 0) ? srcAh : (a == 1) ? srcAl : (a == 2) ? srcBh : srcBl;
                cpasync16(stb + a * ARR_B + (uint32_t)(r * ROW_B + cc * 16),
                          s + (size_t)r * DD + k0 + cc * 8);
            }
            CP_COMMIT();
            CP_WAIT(1);
        } else {
            CP_WAIT(0);
        }
        __syncthreads();

        const uint32_t so = (uint32_t)(it & 1) * STAGE_B;
        #pragma unroll
        for (int ks = 0; ks < 2; ks++) {
            const uint32_t off = so + ks * 32;
            unsigned ah[2][4], al[2][4];
            #pragma unroll
            for (int mb = 0; mb < 2; mb++) {
                ldsm4(ah[mb], cx.aHi[mb] + off);
                ldsm4(al[mb], cx.aLo[mb] + off);
            }
            #pragma unroll
            for (int p = 0; p < 4; p++) {
                unsigned tbh[4], tbl[4];
                ldsm4(tbh, cx.bHi[p] + off);
                ldsm4(tbl, cx.bLo[p] + off);
                #pragma unroll
                for (int mb = 0; mb < 2; mb++)
                    #pragma unroll
                    for (int qn = 0; qn < 2; qn++) {
                        int nb = 2 * p + qn;
                        mma16816(cx.d[mb][nb], ah[mb], &tbh[2 * qn]);
                        mma16816(cx.d[mb][nb], ah[mb], &tbl[2 * qn]);
                        mma16816(cx.d[mb][nb], al[mb], &tbh[2 * qn]);
                    }
            }
        }
        __syncthreads();
    }
}

// ---------------------------------------------------------------------------
// projection + L2 norm -> bf16 hi/lo outputs in [bh][s][k]
// ---------------------------------------------------------------------------
__global__ __launch_bounds__(256) void proj_mma()
{
    extern __shared__ __align__(16) char dsm[];
    const uint32_t sb = smem_u32(dsm);

    const int n0 = blockIdx.x * 128;
    const int m0 = blockIdx.y * 128;
    const int t  = n0 >> 9;
    const int nr = n0 & 511;

    const __nv_bfloat16* srcAh = g_ih + (size_t)t * (SS * BB * DD) + (size_t)m0 * DD;
    const __nv_bfloat16* srcAl = g_il + (size_t)t * (SS * BB * DD) + (size_t)m0 * DD;
    const __nv_bfloat16* srcBh = g_wh + (size_t)t * (DD * DD) + (size_t)nr * DD;
    const __nv_bfloat16* srcBl = g_wl + (size_t)t * (DD * DD) + (size_t)nr * DD;

    __nv_bfloat16* dsth = (t == 0) ? g_qh : (t == 1) ? g_kh : g_vh;
    __nv_bfloat16* dstl = (t == 1) ? g_kl : g_vl;      // unused when t==0
    const bool write_lo = (t != 0);

    MmaCtx cx;
    mma_mainloop(cx, sb, srcAh, srcAl, srcBh, srcBl);

    const int tid = threadIdx.x;
    const int wid = tid >> 5, lane = tid & 31;
    const int wm = (wid & 3) * 32, wn = (wid >> 2) * 64;
    const int r0 = lane >> 2, c0 = lane & 3;
    const int h = (nr >> 6) + (wn >> 6);

    #pragma unroll
    for (int mb = 0; mb < 2; mb++) {
        float ssa = 0.f, ssb = 0.f;
        #pragma unroll
        for (int nb = 0; nb < 8; nb++) {
            float* d = cx.d[mb][nb];
            ssa = fmaf(d[0], d[0], fmaf(d[1], d[1], ssa));
            ssb = fmaf(d[2], d[2], fmaf(d[3], d[3], ssb));
        }
        ssa += __shfl_xor_sync(0xffffffffu, ssa, 1);
        ssa += __shfl_xor_sync(0xffffffffu, ssa, 2);
        ssb += __shfl_xor_sync(0xffffffffu, ssb, 1);
        ssb += __shfl_xor_sync(0xffffffffu, ssb, 2);
        float inva = 1.0f / fmaxf(sqrtf(ssa), 1e-12f);
        float invb = 1.0f / fmaxf(sqrtf(ssb), 1e-12f);

        int ma = m0 + wm + mb * 16 + r0;
        int mb2 = ma + 8;
        int ba = ma & 15, sa = ma >> 4;
        int bbb = mb2 & 15, sbb = mb2 >> 4;
        size_t rowA = (((size_t)(ba * HH + h)) * SS + sa) * KK;
        size_t rowB = (((size_t)(bbb * HH + h)) * SS + sbb) * KK;
        #pragma unroll
        for (int nb = 0; nb < 8; nb++) {
            int kk = ((wn & 63) + nb * 8 + 2 * c0);
            float* d = cx.d[mb][nb];
            unsigned hA, lA, hB, lB;
            split2(d[0] * inva, d[1] * inva, hA, lA);
            split2(d[2] * invb, d[3] * invb, hB, lB);
            *(unsigned*)&dsth[rowA + kk] = hA;
            *(unsigned*)&dsth[rowB + kk] = hB;
            if (write_lo) {
                *(unsigned*)&dstl[rowA + kk] = lA;
                *(unsigned*)&dstl[rowB + kk] = lB;
            }
        }
    }
}

// ---------------------------------------------------------------------------
// output projection: out[m][n] fp32
// ---------------------------------------------------------------------------
__global__ __launch_bounds__(256) void outproj_mma(float* __restrict__ out)
{
    extern __shared__ __align__(16) char dsm[];
    const uint32_t sb = smem_u32(dsm);

    const int n0 = blockIdx.x * 128;
    const int m0 = blockIdx.y * 128;

    MmaCtx cx;
    mma_mainloop(cx, sb, g_ath + (size_t)m0 * DD, g_atl + (size_t)m0 * DD,
                 g_oh + (size_t)n0 * DD, g_ol + (size_t)n0 * DD);

    const int tid = threadIdx.x;
    const int wid = tid >> 5, lane = tid & 31;
    const int wm = (wid & 3) * 32, wn = (wid >> 2) * 64;
    const int r0 = lane >> 2, c0 = lane & 3;

    #pragma unroll
    for (int mb = 0; mb < 2; mb++) {
        int ma = m0 + wm + mb * 16 + r0;
        float* pa = out + (size_t)ma * DD;
        float* pb = out + (size_t)(ma + 8) * DD;
        #pragma unroll
        for (int nb = 0; nb < 8; nb++) {
            int n = n0 + wn + nb * 8 + 2 * c0;
            float* d = cx.d[mb][nb];
            *(float2*)&pa[n] = make_float2(d[0], d[1]);
            *(float2*)&pb[n] = make_float2(d[2], d[3]);
        }
    }
}

// ---------------------------------------------------------------------------
// attention via mma.sync: 128 q-rows per CTA, 8 warps x 16 rows, t-chunks 64.
// scores = Qh·(Kh+Kl); P = exp(s/8) (no-max softmax, bounded scores);
// O += (Ph+Pl)·(Vh+Vl) 3-term. P stays in registers (C-frag == A-frag layout).
// ---------------------------------------------------------------------------
#define AT_ROW   144
#define AT_ARR   (64 * AT_ROW)        // 9216
#define AT_STAGE (4 * AT_ARR)         // 36864
#define ATT_SMEM (2 * AT_STAGE)       // 73728

__global__ __launch_bounds__(256, 2) void attn_mma()
{
    extern __shared__ __align__(16) char dsm[];
    const uint32_t sb = smem_u32(dsm);

    const int tid = threadIdx.x, wid = tid >> 5, lane = tid & 31;
    const int s0 = blockIdx.x * 128;
    const int bh = blockIdx.y;
    const int b = bh >> 3, h = bh & 7;

    const __nv_bfloat16* qh = g_qh + (size_t)bh * SS * KK + (size_t)s0 * KK;
    const __nv_bfloat16* kh = g_kh + (size_t)bh * SS * KK;
    const __nv_bfloat16* kl = g_kl + (size_t)bh * SS * KK;
    const __nv_bfloat16* vh = g_vh + (size_t)bh * SS * KK;
    const __nv_bfloat16* vl = g_vl + (size_t)bh * SS * KK;

    // stage Q (hi only): 128 rows x 64 bf16
    #pragma unroll
    for (int i = 0; i < 4; i++) {
        int idx = tid + i * 256;
        int r = idx >> 3, c = idx & 7;
        cpasync16(sb + (uint32_t)(r * AT_ROW + c * 16), qh + (size_t)r * KK + c * 8);
    }
    CP_COMMIT(); CP_WAIT(0);
    __syncthreads();

    unsigned qf[4][4];
    const int wq0 = wid * 16;
    #pragma unroll
    for (int ks = 0; ks < 4; ks++)
        ldsm4(qf[ks], sb + (uint32_t)((wq0 + (lane & 15)) * AT_ROW)
                        + ks * 32 + (lane >> 4) * 16);
    __syncthreads();

    // chunk loader: kh,kl,vh,vl tiles of 64 rows x 64 bf16
    auto load_chunk = [&](uint32_t stb, int t0) {
        #pragma unroll
        for (int i = 0; i < 8; i++) {
            int idx = tid + i * 256;
            int a = idx >> 9, ci = idx & 511, r = ci >> 3, c = ci & 7;
            const __nv_bfloat16* s =
                (a == 0) ? kh : (a == 1) ? kl : (a == 2) ? vh : vl;
            cpasync16(stb + a * AT_ARR + (uint32_t)(r * AT_ROW + c * 16),
                      s + (size_t)(t0 + r) * KK + c * 8);
        }
    };
    load_chunk(sb, 0); CP_COMMIT();

    float o[8][4] = {};
    float l0 = 0.f, l1 = 0.f;

    for (int c = 0; c < 16; c++) {
        if (c < 15) {
            load_chunk(sb + (uint32_t)((c + 1) & 1) * AT_STAGE, (c + 1) * 64);
            CP_COMMIT(); CP_WAIT(1);
        } else {
            CP_WAIT(0);
        }
        __syncthreads();
        const uint32_t so = sb + (uint32_t)(c & 1) * AT_STAGE;

        // scores: sc[nt] over t-tiles (n = t)
        float sc[8][4] = {};
        #pragma unroll
        for (int ks = 0; ks < 4; ks++) {
            #pragma unroll
            for (int p = 0; p < 4; p++) {
                uint32_t ro = (uint32_t)((p * 16 + (lane >> 4) * 8 + (lane & 7)) * AT_ROW)
                            + ks * 32 + ((lane >> 3) & 1) * 16;
                unsigned kh4[4], kl4[4];
                ldsm4(kh4, so + 0 * AT_ARR + ro);
                ldsm4(kl4, so + 1 * AT_ARR + ro);
                #pragma unroll
                for (int qn = 0; qn < 2; qn++) {
                    mma16816(sc[2 * p + qn], qf[ks], &kh4[2 * qn]);
                    mma16816(sc[2 * p + qn], qf[ks], &kl4[2 * qn]);
                }
            }
        }

        // exp (scores in [-1,1] pre-scale -> no max), accumulate row sums
        float ev[8][4];
        #pragma unroll
        for (int nt = 0; nt < 8; nt++) {
            ev[nt][0] = __expf(sc[nt][0] * 0.125f);
            ev[nt][1] = __expf(sc[nt][1] * 0.125f);
            ev[nt][2] = __expf(sc[nt][2] * 0.125f);
            ev[nt][3] = __expf(sc[nt][3] * 0.125f);
            l0 += ev[nt][0] + ev[nt][1];
            l1 += ev[nt][2] + ev[nt][3];
        }

        // O += P·V, P from registers (C-frag == A-frag layout)
        #pragma unroll
        for (int ts = 0; ts < 4; ts++) {
            unsigned ph[4], pl[4];
            split2(ev[2 * ts][0],     ev[2 * ts][1],     ph[0], pl[0]);
            split2(ev[2 * ts][2],     ev[2 * ts][3],     ph[1], pl[1]);
            split2(ev[2 * ts + 1][0], ev[2 * ts + 1][1], ph[2], pl[2]);
            split2(ev[2 * ts + 1][2], ev[2 * ts + 1][3], ph[3], pl[3]);
            #pragma unroll
            for (int p = 0; p < 4; p++) {
                uint32_t ro = (uint32_t)((ts * 16 + ((lane >> 3) & 1) * 8 + (lane & 7)) * AT_ROW)
                            + (p * 16 + (lane >> 4) * 8) * 2;
                unsigned vh4[4], vl4[4];
                ldsm4t(vh4, so + 2 * AT_ARR + ro);
                ldsm4t(vl4, so + 3 * AT_ARR + ro);
                #pragma unroll
                for (int qn = 0; qn < 2; qn++) {
                    mma16816(o[2 * p + qn], ph, &vh4[2 * qn]);
                    mma16816(o[2 * p + qn], ph, &vl4[2 * qn]);
                    mma16816(o[2 * p + qn], pl, &vh4[2 * qn]);
                }
            }
        }
        __syncthreads();
    }

    // softmax denominators: reduce col-pairs across the quad
    l0 += __shfl_xor_sync(0xffffffffu, l0, 1);
    l0 += __shfl_xor_sync(0xffffffffu, l0, 2);
    l1 += __shfl_xor_sync(0xffffffffu, l1, 1);
    l1 += __shfl_xor_sync(0xffffffffu, l1, 2);
    float inv0 = 1.0f / l0, inv1 = 1.0f / l1;

    const int r0 = lane >> 2, c0 = lane & 3;
    int sA = s0 + wq0 + r0;
    size_t mA = ((size_t)sA * BB + b) * (HH * KK);
    size_t mB = ((size_t)(sA + 8) * BB + b) * (HH * KK);
    #pragma unroll
    for (int nk = 0; nk < 8; nk++) {
        int j = h * KK + nk * 8 + 2 * c0;
        unsigned h0, lo0, h1, lo1;
        split2(o[nk][0] * inv0, o[nk][1] * inv0, h0, lo0);
        split2(o[nk][2] * inv1, o[nk][3] * inv1, h1, lo1);
        *(unsigned*)&g_ath[mA + j] = h0;
        *(unsigned*)&g_atl[mA + j] = lo0;
        *(unsigned*)&g_ath[mB + j] = h1;
        *(unsigned*)&g_atl[mB + j] = lo1;
    }
}

// ---------------------------------------------------------------------------
extern "C" void kernel_launch(void* const* d_in, const int* in_sizes, int n_in,
                              void* d_out, int out_size)
{
    const float* q    = (const float*)d_in[0];
    const float* k    = (const float*)d_in[1];
    const float* v    = (const float*)d_in[2];
    const float* WQ   = (const float*)d_in[3];
    const float* WK   = (const float*)d_in[4];
    const float* WV   = (const float*)d_in[5];
    const float* Wout = (const float*)d_in[6];
    float* out = (float*)d_out;

    cudaFuncSetAttribute(proj_mma,
                         cudaFuncAttributeMaxDynamicSharedMemorySize, MMA_SMEM);
    cudaFuncSetAttribute(outproj_mma,
                         cudaFuncAttributeMaxDynamicSharedMemorySize, MMA_SMEM);
    cudaFuncSetAttribute(attn_mma,
                         cudaFuncAttributeMaxDynamicSharedMemorySize, ATT_SMEM);

    __nv_bfloat16 *ih, *il, *wh, *wl, *oh, *ol;
    cudaGetSymbolAddress((void**)&ih, g_ih);
    cudaGetSymbolAddress((void**)&il, g_il);
    cudaGetSymbolAddress((void**)&wh, g_wh);
    cudaGetSymbolAddress((void**)&wl, g_wl);
    cudaGetSymbolAddress((void**)&oh, g_oh);
    cudaGetSymbolAddress((void**)&ol, g_ol);

    const int nIn4 = SS * BB * DD / 4;
    const int nW4  = DD * DD / 4;
    cvt_split<<<2048, 256>>>((const float4*)q, (uint2*)ih, (uint2*)il, nIn4);
    cvt_split<<<2048, 256>>>((const float4*)k, (uint2*)(ih + SS * BB * DD),
                             (uint2*)(il + SS * BB * DD), nIn4);
    cvt_split<<<2048, 256>>>((const float4*)v, (uint2*)(ih + 2 * SS * BB * DD),
                             (uint2*)(il + 2 * SS * BB * DD), nIn4);
    cvt_split<<<256, 256>>>((const float4*)WQ, (uint2*)wh, (uint2*)wl, nW4);
    cvt_split<<<256, 256>>>((const float4*)WK, (uint2*)(wh + DD * DD),
                            (uint2*)(wl + DD * DD), nW4);
    cvt_split<<<256, 256>>>((const float4*)WV, (uint2*)(wh + 2 * DD * DD),
                            (uint2*)(wl + 2 * DD * DD), nW4);
    cvt_split<<<256, 256>>>((const float4*)Wout, (uint2*)oh, (uint2*)ol, nW4);

    proj_mma<<<dim3(12, 128), 256, MMA_SMEM>>>();
    attn_mma<<<dim3(SS / 128, BB * HH), 256, ATT_SMEM>>>();
    outproj_mma<<<dim3(4, 128), 256, MMA_SMEM>>>(out);
}

// round 10
// speedup vs baseline: 4.7661x; 1.0676x over previous
#include <cuda_runtime.h>
#include <cuda_bf16.h>
#include <math.h>
#include <stdint.h>

#define SS 1024
#define BB 16
#define DD 512
#define HH 8
#define KK 64

using ull = unsigned long long;

// bf16 hi/lo splits of inputs & weights (for proj / outproj GEMMs)
__device__ __nv_bfloat16 g_ih[3 * SS * BB * DD];   // q,k,v inputs [t][m=s*16+b][d]
__device__ __nv_bfloat16 g_il[3 * SS * BB * DD];
__device__ __nv_bfloat16 g_wh[3 * DD * DD];        // WQ,WK,WV [t][n][d]
__device__ __nv_bfloat16 g_wl[3 * DD * DD];
__device__ __nv_bfloat16 g_oh[DD * DD];            // Wout [n][j]
__device__ __nv_bfloat16 g_ol[DD * DD];
// normalized projections, bf16, [bh][s][k]  (K hi only; V hi+lo)
__device__ __nv_bfloat16 g_qh[BB * HH * SS * KK];
__device__ __nv_bfloat16 g_kh[BB * HH * SS * KK];
__device__ __nv_bfloat16 g_vh[BB * HH * SS * KK];
__device__ __nv_bfloat16 g_vl[BB * HH * SS * KK];
// attention output [m = s*16+b][j = h*64+k], bf16 hi/lo
__device__ __nv_bfloat16 g_ath[SS * BB * HH * KK];
__device__ __nv_bfloat16 g_atl[SS * BB * HH * KK];

// ---------------------------------------------------------------------------
// helpers
// ---------------------------------------------------------------------------
__device__ __forceinline__ uint32_t smem_u32(const void* p) {
    uint32_t a;
    asm("{ .reg .u64 t; cvta.to.shared.u64 t, %1; cvt.u32.u64 %0, t; }"
        : "=r"(a) : "l"(p));
    return a;
}

__device__ __forceinline__ unsigned bpack(float lo_elem, float hi_elem) {
    unsigned r;  // lower 16 = bf16(lo_elem), upper 16 = bf16(hi_elem)
    asm("cvt.rn.bf16x2.f32 %0, %1, %2;" : "=r"(r) : "f"(hi_elem), "f"(lo_elem));
    return r;
}
__device__ __forceinline__ void split2(float x, float y, unsigned& hi, unsigned& lo) {
    unsigned h = bpack(x, y);
    float hx = __uint_as_float(h << 16);
    float hy = __uint_as_float(h & 0xffff0000u);
    hi = h;
    lo = bpack(x - hx, y - hy);
}

__device__ __forceinline__ void ldsm4(unsigned* r, uint32_t addr) {
    asm volatile("ldmatrix.sync.aligned.m8n8.x4.shared.b16 {%0,%1,%2,%3}, [%4];"
                 : "=r"(r[0]), "=r"(r[1]), "=r"(r[2]), "=r"(r[3]) : "r"(addr));
}
__device__ __forceinline__ void ldsm4t(unsigned* r, uint32_t addr) {
    asm volatile("ldmatrix.sync.aligned.m8n8.x4.trans.shared.b16 {%0,%1,%2,%3}, [%4];"
                 : "=r"(r[0]), "=r"(r[1]), "=r"(r[2]), "=r"(r[3]) : "r"(addr));
}
__device__ __forceinline__ void mma16816(float* d, const unsigned* a, const unsigned* b) {
    asm volatile("mma.sync.aligned.m16n8k16.row.col.f32.bf16.bf16.f32 "
                 "{%0,%1,%2,%3}, {%4,%5,%6,%7}, {%8,%9}, {%0,%1,%2,%3};"
                 : "+f"(d[0]), "+f"(d[1]), "+f"(d[2]), "+f"(d[3])
                 : "r"(a[0]), "r"(a[1]), "r"(a[2]), "r"(a[3]), "r"(b[0]), "r"(b[1]));
}
__device__ __forceinline__ void cpasync16(uint32_t saddr, const void* gaddr) {
    asm volatile("cp.async.ca.shared.global [%0], [%1], 16;"
                 :: "r"(saddr), "l"(gaddr) : "memory");
}
#define CP_COMMIT() asm volatile("cp.async.commit_group;" ::: "memory")
#define CP_WAIT(n)  asm volatile("cp.async.wait_group %0;" :: "n"(n) : "memory")

// GEMM smem layout: rows of 32 bf16 padded to 80B
#define ROW_B   80
#define ARR_B   10240
#define B_HI    20480
#define B_LO    30720
#define STAGE_B 40960
#define MMA_SMEM (2 * STAGE_B)

// ---------------------------------------------------------------------------
// fused convert: fp32 -> bf16 hi/lo, one launch, z selects array
// ---------------------------------------------------------------------------
__global__ void cvt_all(const float4* __restrict__ q, const float4* __restrict__ k,
                        const float4* __restrict__ v, const float4* __restrict__ wq,
                        const float4* __restrict__ wk, const float4* __restrict__ wv,
                        const float4* __restrict__ wo)
{
    const int NIN = SS * BB * DD / 4, NW = DD * DD / 4;
    const int z = blockIdx.z;
    const float4* src;
    uint2 *hi, *lo;
    int n4;
    switch (z) {
        case 0: src = q;  hi = (uint2*)g_ih;                 lo = (uint2*)g_il;                 n4 = NIN; break;
        case 1: src = k;  hi = (uint2*)g_ih + NIN;           lo = (uint2*)g_il + NIN;           n4 = NIN; break;
        case 2: src = v;  hi = (uint2*)g_ih + 2 * NIN;       lo = (uint2*)g_il + 2 * NIN;       n4 = NIN; break;
        case 3: src = wq; hi = (uint2*)g_wh;                 lo = (uint2*)g_wl;                 n4 = NW;  break;
        case 4: src = wk; hi = (uint2*)g_wh + NW;            lo = (uint2*)g_wl + NW;            n4 = NW;  break;
        case 5: src = wv; hi = (uint2*)g_wh + 2 * NW;        lo = (uint2*)g_wl + 2 * NW;        n4 = NW;  break;
        default: src = wo; hi = (uint2*)g_oh;                lo = (uint2*)g_ol;                 n4 = NW;  break;
    }
    for (int i = blockIdx.x * blockDim.x + threadIdx.x; i < n4;
         i += gridDim.x * blockDim.x) {
        float4 x = src[i];
        unsigned h0, l0, h1, l1;
        split2(x.x, x.y, h0, l0);
        split2(x.z, x.w, h1, l1);
        hi[i] = make_uint2(h0, h1);
        lo[i] = make_uint2(l0, l1);
    }
}

// ---------------------------------------------------------------------------
// shared mma mainloop: 128x128 fp32 tile in d[2][8][4] (3-term hi/lo)
// ---------------------------------------------------------------------------
struct MmaCtx {
    float d[2][8][4];
    uint32_t aHi[2], aLo[2], bHi[4], bLo[4];
};

__device__ __forceinline__ void mma_mainloop(
    MmaCtx& cx, uint32_t sb,
    const __nv_bfloat16* srcAh, const __nv_bfloat16* srcAl,
    const __nv_bfloat16* srcBh, const __nv_bfloat16* srcBl)
{
    const int tid = threadIdx.x;
    const int wid = tid >> 5, lane = tid & 31;
    const int wm = (wid & 3) * 32, wn = (wid >> 2) * 64;

    #pragma unroll
    for (int mb = 0; mb < 2; mb++) {
        uint32_t ro = (uint32_t)(wm + mb * 16 + (lane & 15)) * ROW_B + (lane >> 4) * 16;
        cx.aHi[mb] = sb + ro;
        cx.aLo[mb] = sb + ARR_B + ro;
    }
    #pragma unroll
    for (int p = 0; p < 4; p++) {
        uint32_t ro = (uint32_t)(wn + p * 16 + (lane >> 4) * 8 + (lane & 7)) * ROW_B
                    + ((lane >> 3) & 1) * 16;
        cx.bHi[p] = sb + B_HI + ro;
        cx.bLo[p] = sb + B_LO + ro;
    }
    #pragma unroll
    for (int mb = 0; mb < 2; mb++)
        #pragma unroll
        for (int nb = 0; nb < 8; nb++)
            #pragma unroll
            for (int e = 0; e < 4; e++) cx.d[mb][nb][e] = 0.f;

    {
        #pragma unroll
        for (int i = 0; i < 8; i++) {
            int idx = tid + i * 256;
            int a = idx >> 9, ci = idx & 511, r = ci >> 2, cc = ci & 3;
            const __nv_bfloat16* s =
                (a == 0) ? srcAh : (a == 1) ? srcAl : (a == 2) ? srcBh : srcBl;
            cpasync16(sb + a * ARR_B + (uint32_t)(r * ROW_B + cc * 16),
                      s + (size_t)r * DD + cc * 8);
        }
        CP_COMMIT();
    }

    for (int it = 0; it < 16; it++) {
        if (it + 1 < 16) {
            uint32_t stb = sb + (uint32_t)((it + 1) & 1) * STAGE_B;
            int k0 = (it + 1) * 32;
            #pragma unroll
            for (int i = 0; i < 8; i++) {
                int idx = tid + i * 256;
                int a = idx >> 9, ci = idx & 511, r = ci >> 2, cc = ci & 3;
                const __nv_bfloat16* s =
                    (a == 0) ? srcAh : (a == 1) ? srcAl : (a == 2) ? srcBh : srcBl;
                cpasync16(stb + a * ARR_B + (uint32_t)(r * ROW_B + cc * 16),
                          s + (size_t)r * DD + k0 + cc * 8);
            }
            CP_COMMIT();
            CP_WAIT(1);
        } else {
            CP_WAIT(0);
        }
        __syncthreads();

        const uint32_t so = (uint32_t)(it & 1) * STAGE_B;
        #pragma unroll
        for (int ks = 0; ks < 2; ks++) {
            const uint32_t off = so + ks * 32;
            unsigned ah[2][4], al[2][4];
            #pragma unroll
            for (int mb = 0; mb < 2; mb++) {
                ldsm4(ah[mb], cx.aHi[mb] + off);
                ldsm4(al[mb], cx.aLo[mb] + off);
            }
            #pragma unroll
            for (int p = 0; p < 4; p++) {
                unsigned tbh[4], tbl[4];
                ldsm4(tbh, cx.bHi[p] + off);
                ldsm4(tbl, cx.bLo[p] + off);
                #pragma unroll
                for (int mb = 0; mb < 2; mb++)
                    #pragma unroll
                    for (int qn = 0; qn < 2; qn++) {
                        int nb = 2 * p + qn;
                        mma16816(cx.d[mb][nb], ah[mb], &tbh[2 * qn]);
                        mma16816(cx.d[mb][nb], ah[mb], &tbl[2 * qn]);
                        mma16816(cx.d[mb][nb], al[mb], &tbh[2 * qn]);
                    }
            }
        }
        __syncthreads();
    }
}

// ---------------------------------------------------------------------------
// projection + L2 norm -> bf16 outputs in [bh][s][k]
// ---------------------------------------------------------------------------
__global__ __launch_bounds__(256) void proj_mma()
{
    extern __shared__ __align__(16) char dsm[];
    const uint32_t sb = smem_u32(dsm);

    const int n0 = blockIdx.x * 128;
    const int m0 = blockIdx.y * 128;
    const int t  = n0 >> 9;
    const int nr = n0 & 511;

    const __nv_bfloat16* srcAh = g_ih + (size_t)t * (SS * BB * DD) + (size_t)m0 * DD;
    const __nv_bfloat16* srcAl = g_il + (size_t)t * (SS * BB * DD) + (size_t)m0 * DD;
    const __nv_bfloat16* srcBh = g_wh + (size_t)t * (DD * DD) + (size_t)nr * DD;
    const __nv_bfloat16* srcBl = g_wl + (size_t)t * (DD * DD) + (size_t)nr * DD;

    __nv_bfloat16* dsth = (t == 0) ? g_qh : (t == 1) ? g_kh : g_vh;
    __nv_bfloat16* dstl = g_vl;
    const bool write_lo = (t == 2);     // only V needs the lo residue

    MmaCtx cx;
    mma_mainloop(cx, sb, srcAh, srcAl, srcBh, srcBl);

    const int tid = threadIdx.x;
    const int wid = tid >> 5, lane = tid & 31;
    const int wm = (wid & 3) * 32, wn = (wid >> 2) * 64;
    const int r0 = lane >> 2, c0 = lane & 3;
    const int h = (nr >> 6) + (wn >> 6);

    #pragma unroll
    for (int mb = 0; mb < 2; mb++) {
        float ssa = 0.f, ssb = 0.f;
        #pragma unroll
        for (int nb = 0; nb < 8; nb++) {
            float* d = cx.d[mb][nb];
            ssa = fmaf(d[0], d[0], fmaf(d[1], d[1], ssa));
            ssb = fmaf(d[2], d[2], fmaf(d[3], d[3], ssb));
        }
        ssa += __shfl_xor_sync(0xffffffffu, ssa, 1);
        ssa += __shfl_xor_sync(0xffffffffu, ssa, 2);
        ssb += __shfl_xor_sync(0xffffffffu, ssb, 1);
        ssb += __shfl_xor_sync(0xffffffffu, ssb, 2);
        float inva = 1.0f / fmaxf(sqrtf(ssa), 1e-12f);
        float invb = 1.0f / fmaxf(sqrtf(ssb), 1e-12f);

        int ma = m0 + wm + mb * 16 + r0;
        int mb2 = ma + 8;
        int ba = ma & 15, sa = ma >> 4;
        int bbb = mb2 & 15, sbb = mb2 >> 4;
        size_t rowA = (((size_t)(ba * HH + h)) * SS + sa) * KK;
        size_t rowB = (((size_t)(bbb * HH + h)) * SS + sbb) * KK;
        #pragma unroll
        for (int nb = 0; nb < 8; nb++) {
            int kk = ((wn & 63) + nb * 8 + 2 * c0);
            float* d = cx.d[mb][nb];
            unsigned hA, lA, hB, lB;
            split2(d[0] * inva, d[1] * inva, hA, lA);
            split2(d[2] * invb, d[3] * invb, hB, lB);
            *(unsigned*)&dsth[rowA + kk] = hA;
            *(unsigned*)&dsth[rowB + kk] = hB;
            if (write_lo) {
                *(unsigned*)&dstl[rowA + kk] = lA;
                *(unsigned*)&dstl[rowB + kk] = lB;
            }
        }
    }
}

// ---------------------------------------------------------------------------
// output projection: out[m][n] fp32
// ---------------------------------------------------------------------------
__global__ __launch_bounds__(256) void outproj_mma(float* __restrict__ out)
{
    extern __shared__ __align__(16) char dsm[];
    const uint32_t sb = smem_u32(dsm);

    const int n0 = blockIdx.x * 128;
    const int m0 = blockIdx.y * 128;

    MmaCtx cx;
    mma_mainloop(cx, sb, g_ath + (size_t)m0 * DD, g_atl + (size_t)m0 * DD,
                 g_oh + (size_t)n0 * DD, g_ol + (size_t)n0 * DD);

    const int tid = threadIdx.x;
    const int wid = tid >> 5, lane = tid & 31;
    const int wm = (wid & 3) * 32, wn = (wid >> 2) * 64;
    const int r0 = lane >> 2, c0 = lane & 3;

    #pragma unroll
    for (int mb = 0; mb < 2; mb++) {
        int ma = m0 + wm + mb * 16 + r0;
        float* pa = out + (size_t)ma * DD;
        float* pb = out + (size_t)(ma + 8) * DD;
        #pragma unroll
        for (int nb = 0; nb < 8; nb++) {
            int n = n0 + wn + nb * 8 + 2 * c0;
            float* d = cx.d[mb][nb];
            *(float2*)&pa[n] = make_float2(d[0], d[1]);
            *(float2*)&pb[n] = make_float2(d[2], d[3]);
        }
    }
}

// ---------------------------------------------------------------------------
// attention via mma.sync: 128 q-rows per CTA, 8 warps x 16 rows, t-chunks 64.
// scores = Qh·Kh (unit-vector rounding enters exp(s/8) attenuated -> ok);
// P = exp(s/8) in hi+lo; O += Ph·(Vh+Vl) + Pl·Vh (pl·vl ~1e-5, dropped).
// 3-stage cp.async ring (kh,vh,vl per stage), single sync per chunk.
// ---------------------------------------------------------------------------
#define AT_ROW   144
#define AT_ARR   (64 * AT_ROW)        // 9216
#define AT_STAGE (3 * AT_ARR)         // 27648
#define AT_QOFF  (3 * AT_STAGE)       // 82944
#define ATT_SMEM (AT_QOFF + 128 * AT_ROW)   // 101376

__global__ __launch_bounds__(256, 2) void attn_mma()
{
    extern __shared__ __align__(16) char dsm[];
    const uint32_t sb = smem_u32(dsm);

    const int tid = threadIdx.x, wid = tid >> 5, lane = tid & 31;
    const int s0 = blockIdx.x * 128;
    const int bh = blockIdx.y;
    const int b = bh >> 3, h = bh & 7;

    const __nv_bfloat16* qh = g_qh + (size_t)bh * SS * KK + (size_t)s0 * KK;
    const __nv_bfloat16* kh = g_kh + (size_t)bh * SS * KK;
    const __nv_bfloat16* vh = g_vh + (size_t)bh * SS * KK;
    const __nv_bfloat16* vl = g_vl + (size_t)bh * SS * KK;

    // chunk loader: kh,vh,vl tiles of 64 rows x 64 bf16 (6 chunks/thread)
    auto load_chunk = [&](uint32_t stb, int t0) {
        #pragma unroll
        for (int i = 0; i < 6; i++) {
            int idx = tid + i * 256;
            int a = idx >> 9, ci = idx & 511, r = ci >> 3, c = ci & 7;
            const __nv_bfloat16* s = (a == 0) ? kh : (a == 1) ? vh : vl;
            cpasync16(stb + a * AT_ARR + (uint32_t)(r * AT_ROW + c * 16),
                      s + (size_t)(t0 + r) * KK + c * 8);
        }
    };

    // group 0: Q tile (hi only), 128 rows x 64 bf16
    #pragma unroll
    for (int i = 0; i < 4; i++) {
        int idx = tid + i * 256;
        int r = idx >> 3, c = idx & 7;
        cpasync16(sb + AT_QOFF + (uint32_t)(r * AT_ROW + c * 16),
                  qh + (size_t)r * KK + c * 8);
    }
    CP_COMMIT();
    // groups 1,2: chunks 0,1
    load_chunk(sb, 0); CP_COMMIT();
    load_chunk(sb + AT_STAGE, 64); CP_COMMIT();

    CP_WAIT(2);          // Q ready
    __syncthreads();
    unsigned qf[4][4];
    const int wq0 = wid * 16;
    #pragma unroll
    for (int ks = 0; ks < 4; ks++)
        ldsm4(qf[ks], sb + AT_QOFF + (uint32_t)((wq0 + (lane & 15)) * AT_ROW)
                        + ks * 32 + (lane >> 4) * 16);

    float o[8][4] = {};
    float l0 = 0.f, l1 = 0.f;

    for (int c = 0; c < 16; c++) {
        if (c < 15) { CP_WAIT(1); } else { CP_WAIT(0); }
        __syncthreads();                 // all warps done with stage (c+2)%3's prior use
        if (c + 2 < 16) {
            load_chunk(sb + (uint32_t)((c + 2) % 3) * AT_STAGE, (c + 2) * 64);
            CP_COMMIT();
        }
        const uint32_t so = sb + (uint32_t)(c % 3) * AT_STAGE;

        // scores: Qh . Kh
        float sc[8][4] = {};
        #pragma unroll
        for (int ks = 0; ks < 4; ks++) {
            #pragma unroll
            for (int p = 0; p < 4; p++) {
                uint32_t ro = (uint32_t)((p * 16 + (lane >> 4) * 8 + (lane & 7)) * AT_ROW)
                            + ks * 32 + ((lane >> 3) & 1) * 16;
                unsigned kh4[4];
                ldsm4(kh4, so + ro);
                mma16816(sc[2 * p],     qf[ks], &kh4[0]);
                mma16816(sc[2 * p + 1], qf[ks], &kh4[2]);
            }
        }

        // exp (bounded scores -> no running max), row sums
        float ev[8][4];
        #pragma unroll
        for (int nt = 0; nt < 8; nt++) {
            ev[nt][0] = __expf(sc[nt][0] * 0.125f);
            ev[nt][1] = __expf(sc[nt][1] * 0.125f);
            ev[nt][2] = __expf(sc[nt][2] * 0.125f);
            ev[nt][3] = __expf(sc[nt][3] * 0.125f);
            l0 += ev[nt][0] + ev[nt][1];
            l1 += ev[nt][2] + ev[nt][3];
        }

        // O += Ph·(Vh+Vl) + Pl·Vh   (P hi/lo split: removes bf16 P-rounding bias)
        #pragma unroll
        for (int ts = 0; ts < 4; ts++) {
            unsigned ph[4], pl[4];
            split2(ev[2 * ts][0],     ev[2 * ts][1],     ph[0], pl[0]);
            split2(ev[2 * ts][2],     ev[2 * ts][3],     ph[1], pl[1]);
            split2(ev[2 * ts + 1][0], ev[2 * ts + 1][1], ph[2], pl[2]);
            split2(ev[2 * ts + 1][2], ev[2 * ts + 1][3], ph[3], pl[3]);
            #pragma unroll
            for (int p = 0; p < 4; p++) {
                uint32_t ro = (uint32_t)((ts * 16 + ((lane >> 3) & 1) * 8 + (lane & 7)) * AT_ROW)
                            + (p * 16 + (lane >> 4) * 8) * 2;
                unsigned vh4[4], vl4[4];
                ldsm4t(vh4, so + 1 * AT_ARR + ro);
                ldsm4t(vl4, so + 2 * AT_ARR + ro);
                #pragma unroll
                for (int qn = 0; qn < 2; qn++) {
                    mma16816(o[2 * p + qn], ph, &vh4[2 * qn]);
                    mma16816(o[2 * p + qn], ph, &vl4[2 * qn]);
                    mma16816(o[2 * p + qn], pl, &vh4[2 * qn]);
                }
            }
        }
    }

    // softmax denominators: reduce col-pairs across the quad
    l0 += __shfl_xor_sync(0xffffffffu, l0, 1);
    l0 += __shfl_xor_sync(0xffffffffu, l0, 2);
    l1 += __shfl_xor_sync(0xffffffffu, l1, 1);
    l1 += __shfl_xor_sync(0xffffffffu, l1, 2);
    float inv0 = 1.0f / l0, inv1 = 1.0f / l1;

    const int r0 = lane >> 2, c0 = lane & 3;
    int sA = s0 + wq0 + r0;
    size_t mA = ((size_t)sA * BB + b) * (HH * KK);
    size_t mB = ((size_t)(sA + 8) * BB + b) * (HH * KK);
    #pragma unroll
    for (int nk = 0; nk < 8; nk++) {
        int j = h * KK + nk * 8 + 2 * c0;
        unsigned h0, lo0, h1, lo1;
        split2(o[nk][0] * inv0, o[nk][1] * inv0, h0, lo0);
        split2(o[nk][2] * inv1, o[nk][3] * inv1, h1, lo1);
        *(unsigned*)&g_ath[mA + j] = h0;
        *(unsigned*)&g_atl[mA + j] = lo0;
        *(unsigned*)&g_ath[mB + j] = h1;
        *(unsigned*)&g_atl[mB + j] = lo1;
    }
}

// ---------------------------------------------------------------------------
extern "C" void kernel_launch(void* const* d_in, const int* in_sizes, int n_in,
                              void* d_out, int out_size)
{
    const float* q    = (const float*)d_in[0];
    const float* k    = (const float*)d_in[1];
    const float* v    = (const float*)d_in[2];
    const float* WQ   = (const float*)d_in[3];
    const float* WK   = (const float*)d_in[4];
    const float* WV   = (const float*)d_in[5];
    const float* Wout = (const float*)d_in[6];
    float* out = (float*)d_out;

    cudaFuncSetAttribute(proj_mma,
                         cudaFuncAttributeMaxDynamicSharedMemorySize, MMA_SMEM);
    cudaFuncSetAttribute(outproj_mma,
                         cudaFuncAttributeMaxDynamicSharedMemorySize, MMA_SMEM);
    cudaFuncSetAttribute(attn_mma,
                         cudaFuncAttributeMaxDynamicSharedMemorySize, ATT_SMEM);

    cvt_all<<<dim3(1024, 1, 7), 256>>>((const float4*)q, (const float4*)k,
                                       (const float4*)v, (const float4*)WQ,
                                       (const float4*)WK, (const float4*)WV,
                                       (const float4*)Wout);
    proj_mma<<<dim3(12, 128), 256, MMA_SMEM>>>();
    attn_mma<<<dim3(SS / 128, BB * HH), 256, ATT_SMEM>>>();
    outproj_mma<<<dim3(4, 128), 256, MMA_SMEM>>>(out);
}

// round 11
// speedup vs baseline: 4.8810x; 1.0241x over previous
#include <cuda_runtime.h>
#include <cuda_bf16.h>
#include <math.h>
#include <stdint.h>

#define SS 1024
#define BB 16
#define DD 512
#define HH 8
#define KK 64

using ull = unsigned long long;

// bf16 hi/lo splits of inputs & weights (for proj / outproj GEMMs)
__device__ __nv_bfloat16 g_ih[3 * SS * BB * DD];   // q,k,v inputs [t][m=s*16+b][d]
__device__ __nv_bfloat16 g_il[3 * SS * BB * DD];
__device__ __nv_bfloat16 g_wh[3 * DD * DD];        // WQ,WK,WV [t][n][d]
__device__ __nv_bfloat16 g_wl[3 * DD * DD];
__device__ __nv_bfloat16 g_oh[DD * DD];            // Wout [n][j]
__device__ __nv_bfloat16 g_ol[DD * DD];
// normalized projections, bf16, [bh][s][k]  (K hi only; V hi+lo)
__device__ __nv_bfloat16 g_qh[BB * HH * SS * KK];
__device__ __nv_bfloat16 g_kh[BB * HH * SS * KK];
__device__ __nv_bfloat16 g_vh[BB * HH * SS * KK];
__device__ __nv_bfloat16 g_vl[BB * HH * SS * KK];
// attention output [m = s*16+b][j = h*64+k], bf16 hi/lo
__device__ __nv_bfloat16 g_ath[SS * BB * HH * KK];
__device__ __nv_bfloat16 g_atl[SS * BB * HH * KK];

// ---------------------------------------------------------------------------
// helpers
// ---------------------------------------------------------------------------
__device__ __forceinline__ uint32_t smem_u32(const void* p) {
    uint32_t a;
    asm("{ .reg .u64 t; cvta.to.shared.u64 t, %1; cvt.u32.u64 %0, t; }"
        : "=r"(a) : "l"(p));
    return a;
}

__device__ __forceinline__ unsigned bpack(float lo_elem, float hi_elem) {
    unsigned r;  // lower 16 = bf16(lo_elem), upper 16 = bf16(hi_elem)
    asm("cvt.rn.bf16x2.f32 %0, %1, %2;" : "=r"(r) : "f"(hi_elem), "f"(lo_elem));
    return r;
}
__device__ __forceinline__ void split2(float x, float y, unsigned& hi, unsigned& lo) {
    unsigned h = bpack(x, y);
    float hx = __uint_as_float(h << 16);
    float hy = __uint_as_float(h & 0xffff0000u);
    hi = h;
    lo = bpack(x - hx, y - hy);
}

__device__ __forceinline__ void ldsm4(unsigned* r, uint32_t addr) {
    asm volatile("ldmatrix.sync.aligned.m8n8.x4.shared.b16 {%0,%1,%2,%3}, [%4];"
                 : "=r"(r[0]), "=r"(r[1]), "=r"(r[2]), "=r"(r[3]) : "r"(addr));
}
__device__ __forceinline__ void ldsm4t(unsigned* r, uint32_t addr) {
    asm volatile("ldmatrix.sync.aligned.m8n8.x4.trans.shared.b16 {%0,%1,%2,%3}, [%4];"
                 : "=r"(r[0]), "=r"(r[1]), "=r"(r[2]), "=r"(r[3]) : "r"(addr));
}
// NOTE: non-volatile — pure register computation, lets ptxas interleave
// independent MMAs to hide accumulation latency.
__device__ __forceinline__ void mma16816(float* d, const unsigned* a, const unsigned* b) {
    asm("mma.sync.aligned.m16n8k16.row.col.f32.bf16.bf16.f32 "
        "{%0,%1,%2,%3}, {%4,%5,%6,%7}, {%8,%9}, {%0,%1,%2,%3};"
        : "+f"(d[0]), "+f"(d[1]), "+f"(d[2]), "+f"(d[3])
        : "r"(a[0]), "r"(a[1]), "r"(a[2]), "r"(a[3]), "r"(b[0]), "r"(b[1]));
}
__device__ __forceinline__ void cpasync16(uint32_t saddr, const void* gaddr) {
    asm volatile("cp.async.ca.shared.global [%0], [%1], 16;"
                 :: "r"(saddr), "l"(gaddr) : "memory");
}
#define CP_COMMIT() asm volatile("cp.async.commit_group;" ::: "memory")
#define CP_WAIT(n)  asm volatile("cp.async.wait_group %0;" :: "n"(n) : "memory")

// GEMM smem layout: rows of 32 bf16 padded to 80B
#define ROW_B   80
#define ARR_B   10240
#define B_HI    20480
#define B_LO    30720
#define STAGE_B 40960
#define MMA_SMEM (2 * STAGE_B)

// ---------------------------------------------------------------------------
// fused convert: fp32 -> bf16 hi/lo, one launch, z selects array
// ---------------------------------------------------------------------------
__global__ void cvt_all(const float4* __restrict__ q, const float4* __restrict__ k,
                        const float4* __restrict__ v, const float4* __restrict__ wq,
                        const float4* __restrict__ wk, const float4* __restrict__ wv,
                        const float4* __restrict__ wo)
{
    const int NIN = SS * BB * DD / 4, NW = DD * DD / 4;
    const int z = blockIdx.z;
    const float4* src;
    uint2 *hi, *lo;
    int n4;
    switch (z) {
        case 0: src = q;  hi = (uint2*)g_ih;                 lo = (uint2*)g_il;                 n4 = NIN; break;
        case 1: src = k;  hi = (uint2*)g_ih + NIN;           lo = (uint2*)g_il + NIN;           n4 = NIN; break;
        case 2: src = v;  hi = (uint2*)g_ih + 2 * NIN;       lo = (uint2*)g_il + 2 * NIN;       n4 = NIN; break;
        case 3: src = wq; hi = (uint2*)g_wh;                 lo = (uint2*)g_wl;                 n4 = NW;  break;
        case 4: src = wk; hi = (uint2*)g_wh + NW;            lo = (uint2*)g_wl + NW;            n4 = NW;  break;
        case 5: src = wv; hi = (uint2*)g_wh + 2 * NW;        lo = (uint2*)g_wl + 2 * NW;        n4 = NW;  break;
        default: src = wo; hi = (uint2*)g_oh;                lo = (uint2*)g_ol;                 n4 = NW;  break;
    }
    for (int i = blockIdx.x * blockDim.x + threadIdx.x; i < n4;
         i += gridDim.x * blockDim.x) {
        float4 x = src[i];
        unsigned h0, l0, h1, l1;
        split2(x.x, x.y, h0, l0);
        split2(x.z, x.w, h1, l1);
        hi[i] = make_uint2(h0, h1);
        lo[i] = make_uint2(l0, l1);
    }
}

// ---------------------------------------------------------------------------
// shared mma mainloop: 128x128 fp32 tile in d[2][8][4] (3-term hi/lo)
// term-major MMA order: 4 independent accumulators between reuses.
// ---------------------------------------------------------------------------
struct MmaCtx {
    float d[2][8][4];
    uint32_t aHi[2], aLo[2], bHi[4], bLo[4];
};

__device__ __forceinline__ void mma_mainloop(
    MmaCtx& cx, uint32_t sb,
    const __nv_bfloat16* srcAh, const __nv_bfloat16* srcAl,
    const __nv_bfloat16* srcBh, const __nv_bfloat16* srcBl)
{
    const int tid = threadIdx.x;
    const int wid = tid >> 5, lane = tid & 31;
    const int wm = (wid & 3) * 32, wn = (wid >> 2) * 64;

    #pragma unroll
    for (int mb = 0; mb < 2; mb++) {
        uint32_t ro = (uint32_t)(wm + mb * 16 + (lane & 15)) * ROW_B + (lane >> 4) * 16;
        cx.aHi[mb] = sb + ro;
        cx.aLo[mb] = sb + ARR_B + ro;
    }
    #pragma unroll
    for (int p = 0; p < 4; p++) {
        uint32_t ro = (uint32_t)(wn + p * 16 + (lane >> 4) * 8 + (lane & 7)) * ROW_B
                    + ((lane >> 3) & 1) * 16;
        cx.bHi[p] = sb + B_HI + ro;
        cx.bLo[p] = sb + B_LO + ro;
    }
    #pragma unroll
    for (int mb = 0; mb < 2; mb++)
        #pragma unroll
        for (int nb = 0; nb < 8; nb++)
            #pragma unroll
            for (int e = 0; e < 4; e++) cx.d[mb][nb][e] = 0.f;

    {
        #pragma unroll
        for (int i = 0; i < 8; i++) {
            int idx = tid + i * 256;
            int a = idx >> 9, ci = idx & 511, r = ci >> 2, cc = ci & 3;
            const __nv_bfloat16* s =
                (a == 0) ? srcAh : (a == 1) ? srcAl : (a == 2) ? srcBh : srcBl;
            cpasync16(sb + a * ARR_B + (uint32_t)(r * ROW_B + cc * 16),
                      s + (size_t)r * DD + cc * 8);
        }
        CP_COMMIT();
    }

    for (int it = 0; it < 16; it++) {
        if (it + 1 < 16) {
            uint32_t stb = sb + (uint32_t)((it + 1) & 1) * STAGE_B;
            int k0 = (it + 1) * 32;
            #pragma unroll
            for (int i = 0; i < 8; i++) {
                int idx = tid + i * 256;
                int a = idx >> 9, ci = idx & 511, r = ci >> 2, cc = ci & 3;
                const __nv_bfloat16* s =
                    (a == 0) ? srcAh : (a == 1) ? srcAl : (a == 2) ? srcBh : srcBl;
                cpasync16(stb + a * ARR_B + (uint32_t)(r * ROW_B + cc * 16),
                          s + (size_t)r * DD + k0 + cc * 8);
            }
            CP_COMMIT();
            CP_WAIT(1);
        } else {
            CP_WAIT(0);
        }
        __syncthreads();

        const uint32_t so = (uint32_t)(it & 1) * STAGE_B;
        #pragma unroll
        for (int ks = 0; ks < 2; ks++) {
            const uint32_t off = so + ks * 32;
            unsigned ah[2][4], al[2][4];
            #pragma unroll
            for (int mb = 0; mb < 2; mb++) {
                ldsm4(ah[mb], cx.aHi[mb] + off);
                ldsm4(al[mb], cx.aLo[mb] + off);
            }
            #pragma unroll
            for (int p = 0; p < 4; p++) {
                unsigned tbh[4], tbl[4];
                ldsm4(tbh, cx.bHi[p] + off);
                ldsm4(tbl, cx.bLo[p] + off);
                // term-major: 4 independent accumulators per term
                #pragma unroll
                for (int mb = 0; mb < 2; mb++)
                    #pragma unroll
                    for (int qn = 0; qn < 2; qn++)
                        mma16816(cx.d[mb][2 * p + qn], ah[mb], &tbh[2 * qn]);
                #pragma unroll
                for (int mb = 0; mb < 2; mb++)
                    #pragma unroll
                    for (int qn = 0; qn < 2; qn++)
                        mma16816(cx.d[mb][2 * p + qn], ah[mb], &tbl[2 * qn]);
                #pragma unroll
                for (int mb = 0; mb < 2; mb++)
                    #pragma unroll
                    for (int qn = 0; qn < 2; qn++)
                        mma16816(cx.d[mb][2 * p + qn], al[mb], &tbh[2 * qn]);
            }
        }
        __syncthreads();
    }
}

// ---------------------------------------------------------------------------
// projection + L2 norm -> bf16 outputs in [bh][s][k]
// ---------------------------------------------------------------------------
__global__ __launch_bounds__(256) void proj_mma()
{
    extern __shared__ __align__(16) char dsm[];
    const uint32_t sb = smem_u32(dsm);

    const int n0 = blockIdx.x * 128;
    const int m0 = blockIdx.y * 128;
    const int t  = n0 >> 9;
    const int nr = n0 & 511;

    const __nv_bfloat16* srcAh = g_ih + (size_t)t * (SS * BB * DD) + (size_t)m0 * DD;
    const __nv_bfloat16* srcAl = g_il + (size_t)t * (SS * BB * DD) + (size_t)m0 * DD;
    const __nv_bfloat16* srcBh = g_wh + (size_t)t * (DD * DD) + (size_t)nr * DD;
    const __nv_bfloat16* srcBl = g_wl + (size_t)t * (DD * DD) + (size_t)nr * DD;

    __nv_bfloat16* dsth = (t == 0) ? g_qh : (t == 1) ? g_kh : g_vh;
    __nv_bfloat16* dstl = g_vl;
    const bool write_lo = (t == 2);     // only V needs the lo residue

    MmaCtx cx;
    mma_mainloop(cx, sb, srcAh, srcAl, srcBh, srcBl);

    const int tid = threadIdx.x;
    const int wid = tid >> 5, lane = tid & 31;
    const int wm = (wid & 3) * 32, wn = (wid >> 2) * 64;
    const int r0 = lane >> 2, c0 = lane & 3;
    const int h = (nr >> 6) + (wn >> 6);

    #pragma unroll
    for (int mb = 0; mb < 2; mb++) {
        float ssa = 0.f, ssb = 0.f;
        #pragma unroll
        for (int nb = 0; nb < 8; nb++) {
            float* d = cx.d[mb][nb];
            ssa = fmaf(d[0], d[0], fmaf(d[1], d[1], ssa));
            ssb = fmaf(d[2], d[2], fmaf(d[3], d[3], ssb));
        }
        ssa += __shfl_xor_sync(0xffffffffu, ssa, 1);
        ssa += __shfl_xor_sync(0xffffffffu, ssa, 2);
        ssb += __shfl_xor_sync(0xffffffffu, ssb, 1);
        ssb += __shfl_xor_sync(0xffffffffu, ssb, 2);
        float inva = 1.0f / fmaxf(sqrtf(ssa), 1e-12f);
        float invb = 1.0f / fmaxf(sqrtf(ssb), 1e-12f);

        int ma = m0 + wm + mb * 16 + r0;
        int mb2 = ma + 8;
        int ba = ma & 15, sa = ma >> 4;
        int bbb = mb2 & 15, sbb = mb2 >> 4;
        size_t rowA = (((size_t)(ba * HH + h)) * SS + sa) * KK;
        size_t rowB = (((size_t)(bbb * HH + h)) * SS + sbb) * KK;
        #pragma unroll
        for (int nb = 0; nb < 8; nb++) {
            int kk = ((wn & 63) + nb * 8 + 2 * c0);
            float* d = cx.d[mb][nb];
            unsigned hA, lA, hB, lB;
            split2(d[0] * inva, d[1] * inva, hA, lA);
            split2(d[2] * invb, d[3] * invb, hB, lB);
            *(unsigned*)&dsth[rowA + kk] = hA;
            *(unsigned*)&dsth[rowB + kk] = hB;
            if (write_lo) {
                *(unsigned*)&dstl[rowA + kk] = lA;
                *(unsigned*)&dstl[rowB + kk] = lB;
            }
        }
    }
}

// ---------------------------------------------------------------------------
// output projection: out[m][n] fp32
// ---------------------------------------------------------------------------
__global__ __launch_bounds__(256) void outproj_mma(float* __restrict__ out)
{
    extern __shared__ __align__(16) char dsm[];
    const uint32_t sb = smem_u32(dsm);

    const int n0 = blockIdx.x * 128;
    const int m0 = blockIdx.y * 128;

    MmaCtx cx;
    mma_mainloop(cx, sb, g_ath + (size_t)m0 * DD, g_atl + (size_t)m0 * DD,
                 g_oh + (size_t)n0 * DD, g_ol + (size_t)n0 * DD);

    const int tid = threadIdx.x;
    const int wid = tid >> 5, lane = tid & 31;
    const int wm = (wid & 3) * 32, wn = (wid >> 2) * 64;
    const int r0 = lane >> 2, c0 = lane & 3;

    #pragma unroll
    for (int mb = 0; mb < 2; mb++) {
        int ma = m0 + wm + mb * 16 + r0;
        float* pa = out + (size_t)ma * DD;
        float* pb = out + (size_t)(ma + 8) * DD;
        #pragma unroll
        for (int nb = 0; nb < 8; nb++) {
            int n = n0 + wn + nb * 8 + 2 * c0;
            float* d = cx.d[mb][nb];
            *(float2*)&pa[n] = make_float2(d[0], d[1]);
            *(float2*)&pb[n] = make_float2(d[2], d[3]);
        }
    }
}

// ---------------------------------------------------------------------------
// attention via mma.sync: 128 q-rows per CTA, 8 warps x 16 rows, t-chunks 64.
// scores = Qh·Kh; P = exp(s/8) hi+lo; O += Ph·(Vh+Vl) + Pl·Vh.
// p-pair + term-major MMA ordering for accumulator-chain independence.
// ---------------------------------------------------------------------------
#define AT_ROW   144
#define AT_ARR   (64 * AT_ROW)        // 9216
#define AT_STAGE (3 * AT_ARR)         // 27648
#define AT_QOFF  (3 * AT_STAGE)       // 82944
#define ATT_SMEM (AT_QOFF + 128 * AT_ROW)   // 101376

__global__ __launch_bounds__(256, 2) void attn_mma()
{
    extern __shared__ __align__(16) char dsm[];
    const uint32_t sb = smem_u32(dsm);

    const int tid = threadIdx.x, wid = tid >> 5, lane = tid & 31;
    const int s0 = blockIdx.x * 128;
    const int bh = blockIdx.y;
    const int b = bh >> 3, h = bh & 7;

    const __nv_bfloat16* qh = g_qh + (size_t)bh * SS * KK + (size_t)s0 * KK;
    const __nv_bfloat16* kh = g_kh + (size_t)bh * SS * KK;
    const __nv_bfloat16* vh = g_vh + (size_t)bh * SS * KK;
    const __nv_bfloat16* vl = g_vl + (size_t)bh * SS * KK;

    // chunk loader: kh,vh,vl tiles of 64 rows x 64 bf16 (6 chunks/thread)
    auto load_chunk = [&](uint32_t stb, int t0) {
        #pragma unroll
        for (int i = 0; i < 6; i++) {
            int idx = tid + i * 256;
            int a = idx >> 9, ci = idx & 511, r = ci >> 3, c = ci & 7;
            const __nv_bfloat16* s = (a == 0) ? kh : (a == 1) ? vh : vl;
            cpasync16(stb + a * AT_ARR + (uint32_t)(r * AT_ROW + c * 16),
                      s + (size_t)(t0 + r) * KK + c * 8);
        }
    };

    // group 0: Q tile (hi only), 128 rows x 64 bf16
    #pragma unroll
    for (int i = 0; i < 4; i++) {
        int idx = tid + i * 256;
        int r = idx >> 3, c = idx & 7;
        cpasync16(sb + AT_QOFF + (uint32_t)(r * AT_ROW + c * 16),
                  qh + (size_t)r * KK + c * 8);
    }
    CP_COMMIT();
    // groups 1,2: chunks 0,1
    load_chunk(sb, 0); CP_COMMIT();
    load_chunk(sb + AT_STAGE, 64); CP_COMMIT();

    CP_WAIT(2);          // Q ready
    __syncthreads();
    unsigned qf[4][4];
    const int wq0 = wid * 16;
    #pragma unroll
    for (int ks = 0; ks < 4; ks++)
        ldsm4(qf[ks], sb + AT_QOFF + (uint32_t)((wq0 + (lane & 15)) * AT_ROW)
                        + ks * 32 + (lane >> 4) * 16);

    float o[8][4] = {};
    float l0 = 0.f, l1 = 0.f;

    for (int c = 0; c < 16; c++) {
        if (c < 15) { CP_WAIT(1); } else { CP_WAIT(0); }
        __syncthreads();                 // all warps done with stage (c+2)%3's prior use
        if (c + 2 < 16) {
            load_chunk(sb + (uint32_t)((c + 2) % 3) * AT_STAGE, (c + 2) * 64);
            CP_COMMIT();
        }
        const uint32_t so = sb + (uint32_t)(c % 3) * AT_STAGE;

        // scores: Qh . Kh — p-pairs: 4 independent accumulators in flight
        float sc[8][4] = {};
        #pragma unroll
        for (int ks = 0; ks < 4; ks++) {
            #pragma unroll
            for (int pp = 0; pp < 2; pp++) {
                unsigned kh4a[4], kh4b[4];
                uint32_t roa = (uint32_t)(((2 * pp) * 16 + (lane >> 4) * 8 + (lane & 7)) * AT_ROW)
                             + ks * 32 + ((lane >> 3) & 1) * 16;
                uint32_t rob = roa + 16 * AT_ROW;
                ldsm4(kh4a, so + roa);
                ldsm4(kh4b, so + rob);
                mma16816(sc[4 * pp + 0], qf[ks], &kh4a[0]);
                mma16816(sc[4 * pp + 1], qf[ks], &kh4a[2]);
                mma16816(sc[4 * pp + 2], qf[ks], &kh4b[0]);
                mma16816(sc[4 * pp + 3], qf[ks], &kh4b[2]);
            }
        }

        // exp (bounded scores -> no running max), row sums
        float ev[8][4];
        #pragma unroll
        for (int nt = 0; nt < 8; nt++) {
            ev[nt][0] = __expf(sc[nt][0] * 0.125f);
            ev[nt][1] = __expf(sc[nt][1] * 0.125f);
            ev[nt][2] = __expf(sc[nt][2] * 0.125f);
            ev[nt][3] = __expf(sc[nt][3] * 0.125f);
            l0 += ev[nt][0] + ev[nt][1];
            l1 += ev[nt][2] + ev[nt][3];
        }

        // O += Ph·(Vh+Vl) + Pl·Vh — p-pairs, term-major (4 indep accs per term)
        #pragma unroll
        for (int ts = 0; ts < 4; ts++) {
            unsigned ph[4], pl[4];
            split2(ev[2 * ts][0],     ev[2 * ts][1],     ph[0], pl[0]);
            split2(ev[2 * ts][2],     ev[2 * ts][3],     ph[1], pl[1]);
            split2(ev[2 * ts + 1][0], ev[2 * ts + 1][1], ph[2], pl[2]);
            split2(ev[2 * ts + 1][2], ev[2 * ts + 1][3], ph[3], pl[3]);
            #pragma unroll
            for (int pp = 0; pp < 2; pp++) {
                uint32_t roa = (uint32_t)((ts * 16 + ((lane >> 3) & 1) * 8 + (lane & 7)) * AT_ROW)
                             + ((2 * pp) * 16 + (lane >> 4) * 8) * 2;
                uint32_t rob = roa + 32;
                unsigned vh4a[4], vl4a[4], vh4b[4], vl4b[4];
                ldsm4t(vh4a, so + 1 * AT_ARR + roa);
                ldsm4t(vl4a, so + 2 * AT_ARR + roa);
                ldsm4t(vh4b, so + 1 * AT_ARR + rob);
                ldsm4t(vl4b, so + 2 * AT_ARR + rob);
                // term 1: Ph . Vh
                mma16816(o[4 * pp + 0], ph, &vh4a[0]);
                mma16816(o[4 * pp + 1], ph, &vh4a[2]);
                mma16816(o[4 * pp + 2], ph, &vh4b[0]);
                mma16816(o[4 * pp + 3], ph, &vh4b[2]);
                // term 2: Ph . Vl
                mma16816(o[4 * pp + 0], ph, &vl4a[0]);
                mma16816(o[4 * pp + 1], ph, &vl4a[2]);
                mma16816(o[4 * pp + 2], ph, &vl4b[0]);
                mma16816(o[4 * pp + 3], ph, &vl4b[2]);
                // term 3: Pl . Vh
                mma16816(o[4 * pp + 0], pl, &vh4a[0]);
                mma16816(o[4 * pp + 1], pl, &vh4a[2]);
                mma16816(o[4 * pp + 2], pl, &vh4b[0]);
                mma16816(o[4 * pp + 3], pl, &vh4b[2]);
            }
        }
    }

    // softmax denominators: reduce col-pairs across the quad
    l0 += __shfl_xor_sync(0xffffffffu, l0, 1);
    l0 += __shfl_xor_sync(0xffffffffu, l0, 2);
    l1 += __shfl_xor_sync(0xffffffffu, l1, 1);
    l1 += __shfl_xor_sync(0xffffffffu, l1, 2);
    float inv0 = 1.0f / l0, inv1 = 1.0f / l1;

    const int r0 = lane >> 2, c0 = lane & 3;
    int sA = s0 + wq0 + r0;
    size_t mA = ((size_t)sA * BB + b) * (HH * KK);
    size_t mB = ((size_t)(sA + 8) * BB + b) * (HH * KK);
    #pragma unroll
    for (int nk = 0; nk < 8; nk++) {
        int j = h * KK + nk * 8 + 2 * c0;
        unsigned h0, lo0, h1, lo1;
        split2(o[nk][0] * inv0, o[nk][1] * inv0, h0, lo0);
        split2(o[nk][2] * inv1, o[nk][3] * inv1, h1, lo1);
        *(unsigned*)&g_ath[mA + j] = h0;
        *(unsigned*)&g_atl[mA + j] = lo0;
        *(unsigned*)&g_ath[mB + j] = h1;
        *(unsigned*)&g_atl[mB + j] = lo1;
    }
}

// ---------------------------------------------------------------------------
extern "C" void kernel_launch(void* const* d_in, const int* in_sizes, int n_in,
                              void* d_out, int out_size)
{
    const float* q    = (const float*)d_in[0];
    const float* k    = (const float*)d_in[1];
    const float* v    = (const float*)d_in[2];
    const float* WQ   = (const float*)d_in[3];
    const float* WK   = (const float*)d_in[4];
    const float* WV   = (const float*)d_in[5];
    const float* Wout = (const float*)d_in[6];
    float* out = (float*)d_out;

    cudaFuncSetAttribute(proj_mma,
                         cudaFuncAttributeMaxDynamicSharedMemorySize, MMA_SMEM);
    cudaFuncSetAttribute(outproj_mma,
                         cudaFuncAttributeMaxDynamicSharedMemorySize, MMA_SMEM);
    cudaFuncSetAttribute(attn_mma,
                         cudaFuncAttributeMaxDynamicSharedMemorySize, ATT_SMEM);

    cvt_all<<<dim3(1024, 1, 7), 256>>>((const float4*)q, (const float4*)k,
                                       (const float4*)v, (const float4*)WQ,
                                       (const float4*)WK, (const float4*)WV,
                                       (const float4*)Wout);
    proj_mma<<<dim3(12, 128), 256, MMA_SMEM>>>();
    attn_mma<<<dim3(SS / 128, BB * HH), 256, ATT_SMEM>>>();
    outproj_mma<<<dim3(4, 128), 256, MMA_SMEM>>>(out);
}